// round 13
// baseline (speedup 1.0000x reference)
#include <cuda_runtime.h>
#include <cuda_bf16.h>
#include <cstdint>
#include <cstddef>

// ---------------- problem constants ----------------
#define NB_N   100000
#define NS_N   50000
#define D_N    128
#define NHEADS 8
#define E_BB_N 800000
#define E_SB_N 400000
#define E_BS_N 400000

// ---------------- device scratch (static; no allocation) ----------------
__device__ float g_xb0[(size_t)NB_N * D_N];
__device__ float g_xs0[(size_t)NS_N * D_N];

__device__ float g_acc_bb[(size_t)NB_N * D_N];
__device__ float g_acc_sb[(size_t)NB_N * D_N];
__device__ float g_acc_sb2[(size_t)NB_N * D_N];   // layer-2 sb mean (overlap buffer)
__device__ float g_acc_bs[(size_t)NS_N * D_N];

// CSR structures per edge type
__device__ int g_cnti_bb[NB_N];
__device__ int g_off_bb[NB_N];
__device__ int g_cur_bb[NB_N];
__device__ int g_perm_bb[E_BB_N];
__device__ int g_cnti_sb[NB_N];
__device__ int g_off_sb[NB_N];
__device__ int g_cur_sb[NB_N];
__device__ int g_perm_sb[E_SB_N];
__device__ int g_cnti_bs[NS_N];
__device__ int g_off_bs[NS_N];
__device__ int g_cur_bs[NS_N];
__device__ int g_perm_bs[E_BS_N];

// combined fp32 weights
__device__ float g_Wb[2][384 * 128];
__device__ float g_Bb[2][128];
__device__ float g_Ws[256 * 128];
__device__ float g_Bs[128];

// B in HMMA fragment order: per (ktile, ntile, lane) a uint4 {hi_b0, hi_b1, lo_b0, lo_b1}
__device__ uint4 g_WfragB[2 * 24 * 16 * 32];
__device__ uint4 g_WfragS[16 * 16 * 32];

// ---------------- split-bf16 pack ----------------
__device__ __forceinline__ void split_pack(float v0, float v1, uint32_t& hp, uint32_t& lp) {
    uint32_t b0 = __float_as_uint(v0), b1 = __float_as_uint(v1);
    hp = (b1 & 0xFFFF0000u) | (b0 >> 16);
    float h0 = __uint_as_float(b0 & 0xFFFF0000u);
    float h1 = __uint_as_float(b1 & 0xFFFF0000u);
    asm("cvt.rn.bf16x2.f32 %0, %1, %2;" : "=r"(lp) : "f"(v1 - h1), "f"(v0 - h0));
}

__device__ __forceinline__ void mma_bf16(float* c, const uint32_t* a, uint32_t b0, uint32_t b1) {
    asm volatile("mma.sync.aligned.m16n8k16.row.col.f32.bf16.bf16.f32 "
                 "{%0,%1,%2,%3}, {%4,%5,%6,%7}, {%8,%9}, {%0,%1,%2,%3};"
                 : "+f"(c[0]), "+f"(c[1]), "+f"(c[2]), "+f"(c[3])
                 : "r"(a[0]), "r"(a[1]), "r"(a[2]), "r"(a[3]), "r"(b0), "r"(b1));
}

// ---------------- merged CSR build kernels ----------------
__global__ void zero_all_kernel() {
    int i = blockIdx.x * blockDim.x + threadIdx.x;
    if (i < NB_N)                 g_cnti_bb[i] = 0;
    else if (i < 2 * NB_N)        g_cnti_sb[i - NB_N] = 0;
    else if (i < 2 * NB_N + NS_N) g_cnti_bs[i - 2 * NB_N] = 0;
}
__global__ void count_all_kernel(const int* __restrict__ ei_bb,
                                 const int* __restrict__ ei_sb,
                                 const int* __restrict__ ei_bs) {
    int e = blockIdx.x * blockDim.x + threadIdx.x;
    if (e < E_BB_N) {
        atomicAdd(g_cnti_bb + ei_bb[E_BB_N + e], 1);
    } else if (e < E_BB_N + E_SB_N) {
        int u = e - E_BB_N;
        atomicAdd(g_cnti_sb + ei_sb[E_SB_N + u], 1);
    } else if (e < E_BB_N + E_SB_N + E_BS_N) {
        int u = e - E_BB_N - E_SB_N;
        atomicAdd(g_cnti_bs + ei_bs[E_BS_N + u], 1);
    }
}

// single-kernel exclusive scan: 3 blocks, one per edge type.
__global__ void __launch_bounds__(1024)
scan_all_kernel() {
    __shared__ int sh[1024];
    const int* cnt; int *off, *cur; int n;
    if (blockIdx.x == 0)      { cnt = g_cnti_bb; off = g_off_bb; cur = g_cur_bb; n = NB_N; }
    else if (blockIdx.x == 1) { cnt = g_cnti_sb; off = g_off_sb; cur = g_cur_sb; n = NB_N; }
    else                      { cnt = g_cnti_bs; off = g_off_bs; cur = g_cur_bs; n = NS_N; }
    const int t = threadIdx.x;
    const int chunk = (n + 1023) / 1024;
    const int lo = t * chunk;
    const int hi = min(lo + chunk, n);

    int s = 0;
    for (int i = lo; i < hi; ++i) s += cnt[i];
    sh[t] = s;
    __syncthreads();
    #pragma unroll
    for (int st = 1; st < 1024; st <<= 1) {
        int a = (t >= st) ? sh[t - st] : 0;
        __syncthreads();
        sh[t] += a;
        __syncthreads();
    }
    int running = sh[t] - s;
    for (int i = lo; i < hi; ++i) {
        int v = cnt[i];
        off[i] = running;
        cur[i] = running;
        running += v;
    }
}

__global__ void fill_all_kernel(const int* __restrict__ ei_bb,
                                const int* __restrict__ ei_sb,
                                const int* __restrict__ ei_bs) {
    int e = blockIdx.x * blockDim.x + threadIdx.x;
    if (e < E_BB_N) {
        int p = atomicAdd(g_cur_bb + ei_bb[E_BB_N + e], 1);
        g_perm_bb[p] = ei_bb[e];
    } else if (e < E_BB_N + E_SB_N) {
        int u = e - E_BB_N;
        int p = atomicAdd(g_cur_sb + ei_sb[E_SB_N + u], 1);
        g_perm_sb[p] = ei_sb[u];
    } else if (e < E_BB_N + E_SB_N + E_BS_N) {
        int u = e - E_BB_N - E_SB_N;
        int p = atomicAdd(g_cur_bs + ei_bs[E_BS_N + u], 1);
        g_perm_bs[p] = ei_bs[u];
    }
}

// ---------------- segmented mean core (warp per node, 8-deep MLP) ----------------
__device__ __forceinline__ void segmean_row(const float* __restrict__ x,
                                            const int* __restrict__ perm,
                                            int o, int c, int lane,
                                            float* __restrict__ outrow) {
    float4 acc = make_float4(0.f, 0.f, 0.f, 0.f);
    int i = 0;
    for (; i + 8 <= c; i += 8) {
        float4 v[8];
        #pragma unroll
        for (int j = 0; j < 8; ++j) {
            int s = perm[o + i + j];
            v[j] = reinterpret_cast<const float4*>(x + (size_t)s * D_N)[lane];
        }
        #pragma unroll
        for (int j = 0; j < 8; ++j) {
            acc.x += v[j].x; acc.y += v[j].y; acc.z += v[j].z; acc.w += v[j].w;
        }
    }
    for (; i + 4 <= c; i += 4) {
        float4 v[4];
        #pragma unroll
        for (int j = 0; j < 4; ++j) {
            int s = perm[o + i + j];
            v[j] = reinterpret_cast<const float4*>(x + (size_t)s * D_N)[lane];
        }
        #pragma unroll
        for (int j = 0; j < 4; ++j) {
            acc.x += v[j].x; acc.y += v[j].y; acc.z += v[j].z; acc.w += v[j].w;
        }
    }
    for (; i < c; ++i) {
        int s = perm[o + i];
        float4 v = reinterpret_cast<const float4*>(x + (size_t)s * D_N)[lane];
        acc.x += v.x; acc.y += v.y; acc.z += v.z; acc.w += v.w;
    }
    float inv = (c > 0) ? 1.0f / (float)c : 0.0f;
    acc.x *= inv; acc.y *= inv; acc.z *= inv; acc.w *= inv;
    reinterpret_cast<float4*>(outrow)[lane] = acc;
}

// merged bb + sb segmean (layer 1)
__global__ void __launch_bounds__(256)
segmean2_kernel(const float* __restrict__ xb, const float* __restrict__ xs,
                float* __restrict__ acc_bb, float* __restrict__ acc_sb) {
    int w    = (blockIdx.x * blockDim.x + threadIdx.x) >> 5;
    int lane = threadIdx.x & 31;
    if (w < NB_N) {
        segmean_row(xb, g_perm_bb, g_off_bb[w], g_cnti_bb[w], lane, acc_bb + (size_t)w * D_N);
    } else if (w < 2 * NB_N) {
        int u = w - NB_N;
        segmean_row(xs, g_perm_sb, g_off_sb[u], g_cnti_sb[u], lane, acc_sb + (size_t)u * D_N);
    }
}

__global__ void __launch_bounds__(256)
segmean_bs_kernel(const float* __restrict__ x, float* __restrict__ out) {
    int w    = (blockIdx.x * blockDim.x + threadIdx.x) >> 5;
    int lane = threadIdx.x & 31;
    if (w >= NS_N) return;
    segmean_row(x, g_perm_bs, g_off_bs[w], g_cnti_bs[w], lane, out + (size_t)w * D_N);
}

__global__ void __launch_bounds__(256)
segmean_sb_kernel(const float* __restrict__ x, float* __restrict__ out) {
    int w    = (blockIdx.x * blockDim.x + threadIdx.x) >> 5;
    int lane = threadIdx.x & 31;
    if (w >= NB_N) return;
    segmean_row(x, g_perm_sb, g_off_sb[w], g_cnti_sb[w], lane, out + (size_t)w * D_N);
}

// ---------------- weight prep ----------------
__global__ void prep_wb_kernel(const float* __restrict__ Wl, const float* __restrict__ bl,
                               const float* __restrict__ Wr) {
    int idx = blockIdx.x * blockDim.x + threadIdx.x;
    const int total = 2 * 384 * 128;
    if (idx < total) {
        int l = idx / (384 * 128);
        int r = idx % (384 * 128);
        int k = r / 128, n = r % 128;
        float v;
        if (k < 128)      v = Wl[((size_t)(l * 3 + 0) * 128 + k) * 128 + n];
        else if (k < 256) v = Wl[((size_t)(l * 3 + 1) * 128 + (k - 128)) * 128 + n];
        else              v = Wr[((size_t)(l * 3 + 0) * 128 + (k - 256)) * 128 + n]
                            + Wr[((size_t)(l * 3 + 1) * 128 + (k - 256)) * 128 + n];
        g_Wb[l][r] = v;
    }
    if (idx < 2 * 128) {
        int l = idx / 128, n = idx % 128;
        g_Bb[l][n] = bl[(l * 3 + 0) * 128 + n] + bl[(l * 3 + 1) * 128 + n];
    }
}
__global__ void prep_ws_kernel(const float* __restrict__ Wl, const float* __restrict__ bl,
                               const float* __restrict__ Wr) {
    int idx = blockIdx.x * blockDim.x + threadIdx.x;
    const int total = 256 * 128;
    if (idx < total) {
        int k = idx / 128, n = idx % 128;
        float v;
        if (k < 128) v = Wl[((size_t)2 * 128 + k) * 128 + n];
        else         v = Wr[((size_t)2 * 128 + (k - 128)) * 128 + n];
        g_Ws[idx] = v;
    }
    if (idx < 128) g_Bs[idx] = bl[2 * 128 + idx];
}
__global__ void prep_bfrag_b_kernel() {
    int idx = blockIdx.x * blockDim.x + threadIdx.x;
    if (idx >= 2 * 24 * 16 * 32) return;
    int lane = idx & 31;
    int nt   = (idx >> 5) & 15;
    int t    = idx >> 9;
    int kt   = t % 24;
    int l    = t / 24;
    int n  = nt * 8 + (lane >> 2);
    int k0 = kt * 16 + (lane & 3) * 2;
    const float* W = g_Wb[l];
    float v0 = W[(k0 + 0) * 128 + n], v1 = W[(k0 + 1) * 128 + n];
    float v8 = W[(k0 + 8) * 128 + n], v9 = W[(k0 + 9) * 128 + n];
    uint32_t h0, l0, h1, l1;
    split_pack(v0, v1, h0, l0);
    split_pack(v8, v9, h1, l1);
    g_WfragB[idx] = make_uint4(h0, h1, l0, l1);
}
__global__ void prep_bfrag_s_kernel() {
    int idx = blockIdx.x * blockDim.x + threadIdx.x;
    if (idx >= 16 * 16 * 32) return;
    int lane = idx & 31;
    int nt   = (idx >> 5) & 15;
    int kt   = idx >> 9;
    int n  = nt * 8 + (lane >> 2);
    int k0 = kt * 16 + (lane & 3) * 2;
    float v0 = g_Ws[(k0 + 0) * 128 + n], v1 = g_Ws[(k0 + 1) * 128 + n];
    float v8 = g_Ws[(k0 + 8) * 128 + n], v9 = g_Ws[(k0 + 9) * 128 + n];
    uint32_t h0, l0, h1, l1;
    split_pack(v0, v1, h0, l0);
    split_pack(v8, v9, h1, l1);
    g_WfragS[idx] = make_uint4(h0, h1, l0, l1);
}

// ---------------- HMMA fused GEMM + bias + leaky (+ optional head), smem-staged B ------------
// block: 256 rows x 128 cols; 8 warps stacked in M; warp tile 32x128 (r11 config).
// Optional phase A: per-warp block-local segmean for segment 0 (rows owned by this
// warp only), written to gmem acc then read back by the unchanged GEMM path.
__device__ __forceinline__ void load_rawA(const float* A0, const float* A1, const float* A2,
                                          int kt, int row_lo, int lc, int M,
                                          float2 (&xa)[2][2], float2 (&xb)[2][2]) {
    const int seg = kt >> 3;
    const int kk  = (kt & 7) * 16;
    const float* A = (seg == 0) ? A0 : ((seg == 1) ? A1 : A2);
    #pragma unroll
    for (int mt = 0; mt < 2; ++mt)
        #pragma unroll
        for (int half = 0; half < 2; ++half) {
            int r = row_lo + mt * 16 + half * 8;
            float2 v0 = make_float2(0.f, 0.f), v1 = v0;
            if (r < M) {
                const float* p = A + (size_t)r * D_N + kk + lc;
                v0 = *reinterpret_cast<const float2*>(p);
                v1 = *reinterpret_cast<const float2*>(p + 8);
            }
            xa[mt][half] = v0;
            xb[mt][half] = v1;
        }
}

__global__ void __launch_bounds__(256)
gemm_mma_kernel(const float* A0, const float* A1, const float* A2,
                const uint4* __restrict__ Bfrag, const float* __restrict__ bias,
                float* __restrict__ out, int M, int nseg,
                const float* __restrict__ Wh, const float* __restrict__ bh,
                float* __restrict__ head_out,
                // optional block-local segment-0 mean (phase A)
                const int* __restrict__ perm0, const int* __restrict__ off0,
                const int* __restrict__ cnt0, const float* __restrict__ Xsrc0,
                float* accw0) {
    __shared__ float bsh[128];
    __shared__ float wsh[NHEADS][128];
    __shared__ float bhs[NHEADS];
    __shared__ uint4 bsm[2][512];   // double-buffered 8 KB B k-tile images

    const int tid  = threadIdx.x;
    const int lane = tid & 31;
    const int wid  = tid >> 5;
    const int row0 = blockIdx.x * 256;

    if (tid < 128) bsh[tid] = bias[tid];
    if (head_out) {
        for (int i = tid; i < NHEADS * 128; i += 256) wsh[i >> 7][i & 127] = Wh[i];
        if (tid < NHEADS) bhs[tid] = bh[tid];
    }

    // ---- phase A: block-local segment-0 mean (warp computes its own GEMM rows) ----
    if (perm0) {
        const int rbase = row0 + wid * 32;
        for (int rr = 0; rr < 32; ++rr) {
            int r = rbase + rr;
            if (r < M)
                segmean_row(Xsrc0, perm0, off0[r], cnt0[r], lane, accw0 + (size_t)r * D_N);
        }
    }
    __syncthreads();

    const int K16 = nseg * 8;

    // stage k-tile 0 into buffer 0; prefetch k-tile 1 into regs
    {
        uint4 t0 = Bfrag[tid];
        uint4 t1 = Bfrag[tid + 256];
        bsm[0][tid] = t0;
        bsm[0][tid + 256] = t1;
    }
    uint4 pb0, pb1;
    if (K16 > 1) {
        pb0 = Bfrag[512 + tid];
        pb1 = Bfrag[512 + tid + 256];
    }
    __syncthreads();

    const int lr  = lane >> 2;
    const int lc  = (lane & 3) * 2;
    const int row_lo = row0 + wid * 32 + lr;

    float c[2][16][4] = {};

    float2 ra[2][2], rb[2][2], na[2][2], nb[2][2];
    load_rawA(A0, A1, A2, 0, row_lo, lc, M, ra, rb);

    for (int kt = 0; kt < K16; ++kt) {
        const int cur = kt & 1;
        const int nxt = cur ^ 1;

        if (kt + 1 < K16) {
            bsm[nxt][tid] = pb0;
            bsm[nxt][tid + 256] = pb1;
        }
        if (kt + 2 < K16) {
            pb0 = Bfrag[(size_t)(kt + 2) * 512 + tid];
            pb1 = Bfrag[(size_t)(kt + 2) * 512 + tid + 256];
        }
        if (kt + 1 < K16)
            load_rawA(A0, A1, A2, kt + 1, row_lo, lc, M, na, nb);

        uint32_t ah[2][4], al[2][4];
        #pragma unroll
        for (int mt = 0; mt < 2; ++mt)
            #pragma unroll
            for (int half = 0; half < 2; ++half) {
                split_pack(ra[mt][half].x, ra[mt][half].y, ah[mt][half], al[mt][half]);
                split_pack(rb[mt][half].x, rb[mt][half].y, ah[mt][2 + half], al[mt][2 + half]);
            }

        #pragma unroll
        for (int nt = 0; nt < 16; ++nt) {
            uint4 b = bsm[cur][nt * 32 + lane];
            #pragma unroll
            for (int mt = 0; mt < 2; ++mt) {
                mma_bf16(c[mt][nt], ah[mt], b.x, b.y);
                mma_bf16(c[mt][nt], al[mt], b.x, b.y);
                mma_bf16(c[mt][nt], ah[mt], b.z, b.w);
            }
        }
        __syncthreads();

        #pragma unroll
        for (int mt = 0; mt < 2; ++mt)
            #pragma unroll
            for (int half = 0; half < 2; ++half) {
                ra[mt][half] = na[mt][half];
                rb[mt][half] = nb[mt][half];
            }
    }

    if (head_out) {
        #pragma unroll
        for (int mt = 0; mt < 2; ++mt) {
            #pragma unroll
            for (int half = 0; half < 2; ++half) {
                int r = row_lo + mt * 16 + half * 8;
                float hp[NHEADS] = {};
                #pragma unroll
                for (int nt = 0; nt < 16; ++nt) {
                    int col = nt * 8 + lc;
                    float v0 = c[mt][nt][half * 2 + 0] + bsh[col];
                    float v1 = c[mt][nt][half * 2 + 1] + bsh[col + 1];
                    v0 = v0 > 0.f ? v0 : 0.01f * v0;
                    v1 = v1 > 0.f ? v1 : 0.01f * v1;
                    #pragma unroll
                    for (int h = 0; h < NHEADS; ++h)
                        hp[h] += v0 * wsh[h][col] + v1 * wsh[h][col + 1];
                }
                #pragma unroll
                for (int h = 0; h < NHEADS; ++h) {
                    hp[h] += __shfl_down_sync(0xffffffffu, hp[h], 2, 4);
                    hp[h] += __shfl_down_sync(0xffffffffu, hp[h], 1, 4);
                }
                if ((lane & 3) == 0 && r < M) {
                    float4 o0 = make_float4(hp[0] + bhs[0], hp[1] + bhs[1],
                                            hp[2] + bhs[2], hp[3] + bhs[3]);
                    float4 o1 = make_float4(hp[4] + bhs[4], hp[5] + bhs[5],
                                            hp[6] + bhs[6], hp[7] + bhs[7]);
                    *reinterpret_cast<float4*>(head_out + (size_t)r * NHEADS)     = o0;
                    *reinterpret_cast<float4*>(head_out + (size_t)r * NHEADS + 4) = o1;
                }
            }
        }
    } else {
        #pragma unroll
        for (int mt = 0; mt < 2; ++mt) {
            #pragma unroll
            for (int nt = 0; nt < 16; ++nt) {
                int col = nt * 8 + lc;
                float b0 = bsh[col], b1 = bsh[col + 1];
                int r0 = row_lo + mt * 16;
                int r1 = r0 + 8;
                if (r0 < M) {
                    float2 o;
                    o.x = c[mt][nt][0] + b0; o.x = o.x > 0.f ? o.x : 0.01f * o.x;
                    o.y = c[mt][nt][1] + b1; o.y = o.y > 0.f ? o.y : 0.01f * o.y;
                    *reinterpret_cast<float2*>(out + (size_t)r0 * D_N + col) = o;
                }
                if (r1 < M) {
                    float2 o;
                    o.x = c[mt][nt][2] + b0; o.x = o.x > 0.f ? o.x : 0.01f * o.x;
                    o.y = c[mt][nt][3] + b1; o.y = o.y > 0.f ? o.y : 0.01f * o.y;
                    *reinterpret_cast<float2*>(out + (size_t)r1 * D_N + col) = o;
                }
            }
        }
    }
}

// ---------------- host launch ----------------
extern "C" void kernel_launch(void* const* d_in, const int* in_sizes, int n_in,
                              void* d_out, int out_size) {
    (void)in_sizes; (void)n_in; (void)out_size;
    const float* x_b  = (const float*)d_in[0];
    const float* x_s  = (const float*)d_in[1];
    const float* Wl   = (const float*)d_in[2];
    const float* bl   = (const float*)d_in[3];
    const float* Wr   = (const float*)d_in[4];
    const float* Wh   = (const float*)d_in[5];
    const float* bh   = (const float*)d_in[6];
    const int*   ei_bb = (const int*)d_in[7];   // JAX x64 off -> int32 indices
    const int*   ei_sb = (const int*)d_in[8];
    const int*   ei_bs = (const int*)d_in[9];

    static cudaStream_t sB = nullptr;
    static cudaEvent_t evFork, evPrep, evFill, evS;
    if (!sB) {
        cudaStreamCreateWithFlags(&sB, cudaStreamNonBlocking);
        cudaEventCreateWithFlags(&evFork, cudaEventDisableTiming);
        cudaEventCreateWithFlags(&evPrep, cudaEventDisableTiming);
        cudaEventCreateWithFlags(&evFill, cudaEventDisableTiming);
        cudaEventCreateWithFlags(&evS,    cudaEventDisableTiming);
    }

    void *p_xb0, *p_xs0, *p_abb, *p_asb, *p_asb2, *p_abs, *p_Bb, *p_Bs, *p_FB, *p_FS;
    void *p_perm_bb, *p_off_bb, *p_cnt_bb;
    cudaGetSymbolAddress(&p_xb0, g_xb0);
    cudaGetSymbolAddress(&p_xs0, g_xs0);
    cudaGetSymbolAddress(&p_abb, g_acc_bb); cudaGetSymbolAddress(&p_asb, g_acc_sb);
    cudaGetSymbolAddress(&p_asb2, g_acc_sb2);
    cudaGetSymbolAddress(&p_abs, g_acc_bs);
    cudaGetSymbolAddress(&p_Bb, g_Bb); cudaGetSymbolAddress(&p_Bs, g_Bs);
    cudaGetSymbolAddress(&p_FB, g_WfragB); cudaGetSymbolAddress(&p_FS, g_WfragS);
    cudaGetSymbolAddress(&p_perm_bb, g_perm_bb);
    cudaGetSymbolAddress(&p_off_bb, g_off_bb);
    cudaGetSymbolAddress(&p_cnt_bb, g_cnti_bb);

    float* xb0 = (float*)p_xb0;
    float* xs0 = (float*)p_xs0;
    float* acc_bb = (float*)p_abb; float* acc_sb = (float*)p_asb;
    float* acc_sb2 = (float*)p_asb2; float* acc_bs = (float*)p_abs;
    float* Bbp = (float*)p_Bb; float* Bsp = (float*)p_Bs;
    const uint4* FragB = (const uint4*)p_FB;
    const uint4* FragS = (const uint4*)p_FS;
    const int* perm_bb = (const int*)p_perm_bb;
    const int* off_bb  = (const int*)p_off_bb;
    const int* cnt_bb  = (const int*)p_cnt_bb;

    const int T = 256;
    const int NTOT = 2 * NB_N + NS_N;
    const int ETOT = E_BB_N + E_SB_N + E_BS_N;

    // ---- fork ----
    cudaEventRecord(evFork, 0);
    cudaStreamWaitEvent(sB, evFork, 0);

    // stream 0: CSR build
    zero_all_kernel<<<(NTOT + T - 1) / T, T>>>();
    count_all_kernel<<<(ETOT + T - 1) / T, T>>>(ei_bb, ei_sb, ei_bs);
    scan_all_kernel<<<3, 1024>>>();
    fill_all_kernel<<<(ETOT + T - 1) / T, T>>>(ei_bb, ei_sb, ei_bs);
    cudaEventRecord(evFill, 0);

    // sB: weight prep (independent of CSR)
    prep_wb_kernel<<<(2 * 384 * 128 + T - 1) / T, T, 0, sB>>>(Wl, bl, Wr);
    prep_ws_kernel<<<(256 * 128 + T - 1) / T, T, 0, sB>>>(Wl, bl, Wr);
    prep_bfrag_b_kernel<<<(2 * 24 * 16 * 32 + T - 1) / T, T, 0, sB>>>();
    prep_bfrag_s_kernel<<<(16 * 16 * 32 + T - 1) / T, T, 0, sB>>>();
    cudaEventRecord(evPrep, sB);

    // stream 0: layer-1 b segmeans (needs CSR only)
    segmean2_kernel<<<(2 * NB_N + 7) / 8, 256>>>(x_b, x_s, acc_bb, acc_sb);

    // sB: s-chain + layer-2 sb segmean
    cudaStreamWaitEvent(sB, evFill, 0);
    segmean_bs_kernel<<<(NS_N + 7) / 8, 256, 0, sB>>>(x_b, acc_bs);
    gemm_mma_kernel<<<(NS_N + 255) / 256, 256, 0, sB>>>(
        acc_bs, x_s, nullptr, FragS, Bsp, xs0, NS_N, 2, nullptr, nullptr, nullptr,
        nullptr, nullptr, nullptr, nullptr, nullptr);
    segmean_sb_kernel<<<(NB_N + 7) / 8, 256, 0, sB>>>(xs0, acc_sb2);
    cudaEventRecord(evS, sB);

    // stream 0: layer-1 b GEMM (needs prep)
    cudaStreamWaitEvent(0, evPrep, 0);
    gemm_mma_kernel<<<(NB_N + 255) / 256, 256>>>(
        acc_bb, acc_sb, x_b, FragB, Bbp, xb0, NB_N, 3, nullptr, nullptr, nullptr,
        nullptr, nullptr, nullptr, nullptr, nullptr);

    // stream 0: layer-2 b GEMM with fused bb-mean (phase A) + head readout
    cudaStreamWaitEvent(0, evS, 0);
    gemm_mma_kernel<<<(NB_N + 255) / 256, 256>>>(
        acc_bb, acc_sb2, xb0, FragB + (size_t)24 * 16 * 32, Bbp + 128,
        nullptr, NB_N, 3, Wh, bh, (float*)d_out,
        perm_bb, off_bb, cnt_bb, xb0, acc_bb);
}

// round 14
// speedup vs baseline: 1.1956x; 1.1956x over previous
#include <cuda_runtime.h>
#include <cuda_bf16.h>
#include <cstdint>
#include <cstddef>

// ---------------- problem constants ----------------
#define NB_N   100000
#define NS_N   50000
#define D_N    128
#define NHEADS 8
#define E_BB_N 800000
#define E_SB_N 400000
#define E_BS_N 400000

// ---------------- device scratch (static; no allocation) ----------------
__device__ float g_xb0[(size_t)NB_N * D_N];
__device__ float g_xs0[(size_t)NS_N * D_N];

__device__ float g_acc_bb[(size_t)NB_N * D_N];
__device__ float g_acc_sb[(size_t)NB_N * D_N];
__device__ float g_acc_sb2[(size_t)NB_N * D_N];   // layer-2 sb mean (overlap buffer)
__device__ float g_acc_bs[(size_t)NS_N * D_N];

// CSR structures per edge type
__device__ int g_cnti_bb[NB_N];
__device__ int g_off_bb[NB_N];
__device__ int g_cur_bb[NB_N];
__device__ int g_perm_bb[E_BB_N];
__device__ int g_cnti_sb[NB_N];
__device__ int g_off_sb[NB_N];
__device__ int g_cur_sb[NB_N];
__device__ int g_perm_sb[E_SB_N];
__device__ int g_cnti_bs[NS_N];
__device__ int g_off_bs[NS_N];
__device__ int g_cur_bs[NS_N];
__device__ int g_perm_bs[E_BS_N];

// combined fp32 weights
__device__ float g_Wb[2][384 * 128];
__device__ float g_Bb[2][128];
__device__ float g_Ws[256 * 128];
__device__ float g_Bs[128];

// B in HMMA fragment order: per (ktile, ntile, lane) a uint4 {hi_b0, hi_b1, lo_b0, lo_b1}
__device__ uint4 g_WfragB[2 * 24 * 16 * 32];
__device__ uint4 g_WfragS[16 * 16 * 32];

// ---------------- split-bf16 pack ----------------
__device__ __forceinline__ void split_pack(float v0, float v1, uint32_t& hp, uint32_t& lp) {
    uint32_t b0 = __float_as_uint(v0), b1 = __float_as_uint(v1);
    hp = (b1 & 0xFFFF0000u) | (b0 >> 16);
    float h0 = __uint_as_float(b0 & 0xFFFF0000u);
    float h1 = __uint_as_float(b1 & 0xFFFF0000u);
    asm("cvt.rn.bf16x2.f32 %0, %1, %2;" : "=r"(lp) : "f"(v1 - h1), "f"(v0 - h0));
}

__device__ __forceinline__ void mma_bf16(float* c, const uint32_t* a, uint32_t b0, uint32_t b1) {
    asm volatile("mma.sync.aligned.m16n8k16.row.col.f32.bf16.bf16.f32 "
                 "{%0,%1,%2,%3}, {%4,%5,%6,%7}, {%8,%9}, {%0,%1,%2,%3};"
                 : "+f"(c[0]), "+f"(c[1]), "+f"(c[2]), "+f"(c[3])
                 : "r"(a[0]), "r"(a[1]), "r"(a[2]), "r"(a[3]), "r"(b0), "r"(b1));
}

// ---------------- merged CSR build kernels ----------------
__global__ void zero_all_kernel() {
    int i = blockIdx.x * blockDim.x + threadIdx.x;
    if (i < NB_N)                 g_cnti_bb[i] = 0;
    else if (i < 2 * NB_N)        g_cnti_sb[i - NB_N] = 0;
    else if (i < 2 * NB_N + NS_N) g_cnti_bs[i - 2 * NB_N] = 0;
}
__global__ void count_all_kernel(const int* __restrict__ ei_bb,
                                 const int* __restrict__ ei_sb,
                                 const int* __restrict__ ei_bs) {
    int e = blockIdx.x * blockDim.x + threadIdx.x;
    if (e < E_BB_N) {
        atomicAdd(g_cnti_bb + ei_bb[E_BB_N + e], 1);
    } else if (e < E_BB_N + E_SB_N) {
        int u = e - E_BB_N;
        atomicAdd(g_cnti_sb + ei_sb[E_SB_N + u], 1);
    } else if (e < E_BB_N + E_SB_N + E_BS_N) {
        int u = e - E_BB_N - E_SB_N;
        atomicAdd(g_cnti_bs + ei_bs[E_BS_N + u], 1);
    }
}

// single-kernel exclusive scan: 3 blocks, one per edge type.
__global__ void __launch_bounds__(1024)
scan_all_kernel() {
    __shared__ int sh[1024];
    const int* cnt; int *off, *cur; int n;
    if (blockIdx.x == 0)      { cnt = g_cnti_bb; off = g_off_bb; cur = g_cur_bb; n = NB_N; }
    else if (blockIdx.x == 1) { cnt = g_cnti_sb; off = g_off_sb; cur = g_cur_sb; n = NB_N; }
    else                      { cnt = g_cnti_bs; off = g_off_bs; cur = g_cur_bs; n = NS_N; }
    const int t = threadIdx.x;
    const int chunk = (n + 1023) / 1024;
    const int lo = t * chunk;
    const int hi = min(lo + chunk, n);

    int s = 0;
    for (int i = lo; i < hi; ++i) s += cnt[i];
    sh[t] = s;
    __syncthreads();
    #pragma unroll
    for (int st = 1; st < 1024; st <<= 1) {
        int a = (t >= st) ? sh[t - st] : 0;
        __syncthreads();
        sh[t] += a;
        __syncthreads();
    }
    int running = sh[t] - s;
    for (int i = lo; i < hi; ++i) {
        int v = cnt[i];
        off[i] = running;
        cur[i] = running;
        running += v;
    }
}

__global__ void fill_all_kernel(const int* __restrict__ ei_bb,
                                const int* __restrict__ ei_sb,
                                const int* __restrict__ ei_bs) {
    int e = blockIdx.x * blockDim.x + threadIdx.x;
    if (e < E_BB_N) {
        int p = atomicAdd(g_cur_bb + ei_bb[E_BB_N + e], 1);
        g_perm_bb[p] = ei_bb[e];
    } else if (e < E_BB_N + E_SB_N) {
        int u = e - E_BB_N;
        int p = atomicAdd(g_cur_sb + ei_sb[E_SB_N + u], 1);
        g_perm_sb[p] = ei_sb[u];
    } else if (e < E_BB_N + E_SB_N + E_BS_N) {
        int u = e - E_BB_N - E_SB_N;
        int p = atomicAdd(g_cur_bs + ei_bs[E_BS_N + u], 1);
        g_perm_bs[p] = ei_bs[u];
    }
}

// ---------------- segmented mean core (warp per node, 8-deep MLP) ----------------
__device__ __forceinline__ void segmean_row(const float* __restrict__ x,
                                            const int* __restrict__ perm,
                                            int o, int c, int lane,
                                            float* __restrict__ outrow) {
    float4 acc = make_float4(0.f, 0.f, 0.f, 0.f);
    int i = 0;
    for (; i + 8 <= c; i += 8) {
        float4 v[8];
        #pragma unroll
        for (int j = 0; j < 8; ++j) {
            int s = perm[o + i + j];
            v[j] = reinterpret_cast<const float4*>(x + (size_t)s * D_N)[lane];
        }
        #pragma unroll
        for (int j = 0; j < 8; ++j) {
            acc.x += v[j].x; acc.y += v[j].y; acc.z += v[j].z; acc.w += v[j].w;
        }
    }
    for (; i + 4 <= c; i += 4) {
        float4 v[4];
        #pragma unroll
        for (int j = 0; j < 4; ++j) {
            int s = perm[o + i + j];
            v[j] = reinterpret_cast<const float4*>(x + (size_t)s * D_N)[lane];
        }
        #pragma unroll
        for (int j = 0; j < 4; ++j) {
            acc.x += v[j].x; acc.y += v[j].y; acc.z += v[j].z; acc.w += v[j].w;
        }
    }
    for (; i < c; ++i) {
        int s = perm[o + i];
        float4 v = reinterpret_cast<const float4*>(x + (size_t)s * D_N)[lane];
        acc.x += v.x; acc.y += v.y; acc.z += v.z; acc.w += v.w;
    }
    float inv = (c > 0) ? 1.0f / (float)c : 0.0f;
    acc.x *= inv; acc.y *= inv; acc.z *= inv; acc.w *= inv;
    reinterpret_cast<float4*>(outrow)[lane] = acc;
}

// merged bb + sb segmean (layer 1)
__global__ void __launch_bounds__(256)
segmean2_kernel(const float* __restrict__ xb, const float* __restrict__ xs,
                float* __restrict__ acc_bb, float* __restrict__ acc_sb) {
    int w    = (blockIdx.x * blockDim.x + threadIdx.x) >> 5;
    int lane = threadIdx.x & 31;
    if (w < NB_N) {
        segmean_row(xb, g_perm_bb, g_off_bb[w], g_cnti_bb[w], lane, acc_bb + (size_t)w * D_N);
    } else if (w < 2 * NB_N) {
        int u = w - NB_N;
        segmean_row(xs, g_perm_sb, g_off_sb[u], g_cnti_sb[u], lane, acc_sb + (size_t)u * D_N);
    }
}

__global__ void __launch_bounds__(256)
segmean_bs_kernel(const float* __restrict__ x, float* __restrict__ out) {
    int w    = (blockIdx.x * blockDim.x + threadIdx.x) >> 5;
    int lane = threadIdx.x & 31;
    if (w >= NS_N) return;
    segmean_row(x, g_perm_bs, g_off_bs[w], g_cnti_bs[w], lane, out + (size_t)w * D_N);
}

__global__ void __launch_bounds__(256)
segmean_sb_kernel(const float* __restrict__ x, float* __restrict__ out) {
    int w    = (blockIdx.x * blockDim.x + threadIdx.x) >> 5;
    int lane = threadIdx.x & 31;
    if (w >= NB_N) return;
    segmean_row(x, g_perm_sb, g_off_sb[w], g_cnti_sb[w], lane, out + (size_t)w * D_N);
}

__global__ void __launch_bounds__(256)
segmean_bb_kernel(const float* __restrict__ x, float* __restrict__ out) {
    int w    = (blockIdx.x * blockDim.x + threadIdx.x) >> 5;
    int lane = threadIdx.x & 31;
    if (w >= NB_N) return;
    segmean_row(x, g_perm_bb, g_off_bb[w], g_cnti_bb[w], lane, out + (size_t)w * D_N);
}

// ---------------- weight prep ----------------
__global__ void prep_wb_kernel(const float* __restrict__ Wl, const float* __restrict__ bl,
                               const float* __restrict__ Wr) {
    int idx = blockIdx.x * blockDim.x + threadIdx.x;
    const int total = 2 * 384 * 128;
    if (idx < total) {
        int l = idx / (384 * 128);
        int r = idx % (384 * 128);
        int k = r / 128, n = r % 128;
        float v;
        if (k < 128)      v = Wl[((size_t)(l * 3 + 0) * 128 + k) * 128 + n];
        else if (k < 256) v = Wl[((size_t)(l * 3 + 1) * 128 + (k - 128)) * 128 + n];
        else              v = Wr[((size_t)(l * 3 + 0) * 128 + (k - 256)) * 128 + n]
                            + Wr[((size_t)(l * 3 + 1) * 128 + (k - 256)) * 128 + n];
        g_Wb[l][r] = v;
    }
    if (idx < 2 * 128) {
        int l = idx / 128, n = idx % 128;
        g_Bb[l][n] = bl[(l * 3 + 0) * 128 + n] + bl[(l * 3 + 1) * 128 + n];
    }
}
__global__ void prep_ws_kernel(const float* __restrict__ Wl, const float* __restrict__ bl,
                               const float* __restrict__ Wr) {
    int idx = blockIdx.x * blockDim.x + threadIdx.x;
    const int total = 256 * 128;
    if (idx < total) {
        int k = idx / 128, n = idx % 128;
        float v;
        if (k < 128) v = Wl[((size_t)2 * 128 + k) * 128 + n];
        else         v = Wr[((size_t)2 * 128 + (k - 128)) * 128 + n];
        g_Ws[idx] = v;
    }
    if (idx < 128) g_Bs[idx] = bl[2 * 128 + idx];
}
__global__ void prep_bfrag_b_kernel() {
    int idx = blockIdx.x * blockDim.x + threadIdx.x;
    if (idx >= 2 * 24 * 16 * 32) return;
    int lane = idx & 31;
    int nt   = (idx >> 5) & 15;
    int t    = idx >> 9;
    int kt   = t % 24;
    int l    = t / 24;
    int n  = nt * 8 + (lane >> 2);
    int k0 = kt * 16 + (lane & 3) * 2;
    const float* W = g_Wb[l];
    float v0 = W[(k0 + 0) * 128 + n], v1 = W[(k0 + 1) * 128 + n];
    float v8 = W[(k0 + 8) * 128 + n], v9 = W[(k0 + 9) * 128 + n];
    uint32_t h0, l0, h1, l1;
    split_pack(v0, v1, h0, l0);
    split_pack(v8, v9, h1, l1);
    g_WfragB[idx] = make_uint4(h0, h1, l0, l1);
}
__global__ void prep_bfrag_s_kernel() {
    int idx = blockIdx.x * blockDim.x + threadIdx.x;
    if (idx >= 16 * 16 * 32) return;
    int lane = idx & 31;
    int nt   = (idx >> 5) & 15;
    int kt   = idx >> 9;
    int n  = nt * 8 + (lane >> 2);
    int k0 = kt * 16 + (lane & 3) * 2;
    float v0 = g_Ws[(k0 + 0) * 128 + n], v1 = g_Ws[(k0 + 1) * 128 + n];
    float v8 = g_Ws[(k0 + 8) * 128 + n], v9 = g_Ws[(k0 + 9) * 128 + n];
    uint32_t h0, l0, h1, l1;
    split_pack(v0, v1, h0, l0);
    split_pack(v8, v9, h1, l1);
    g_WfragS[idx] = make_uint4(h0, h1, l0, l1);
}

// ---------------- HMMA fused GEMM + bias + leaky (+ optional head), smem-staged B ------------
// r11 champion config: 256 threads, 8 warps stacked in M, warp tile 32x128.
__device__ __forceinline__ void load_rawA(const float* __restrict__ A0,
                                          const float* __restrict__ A1,
                                          const float* __restrict__ A2,
                                          int kt, int row_lo, int lc, int M,
                                          float2 (&xa)[2][2], float2 (&xb)[2][2]) {
    const int seg = kt >> 3;
    const int kk  = (kt & 7) * 16;
    const float* A = (seg == 0) ? A0 : ((seg == 1) ? A1 : A2);
    #pragma unroll
    for (int mt = 0; mt < 2; ++mt)
        #pragma unroll
        for (int half = 0; half < 2; ++half) {
            int r = row_lo + mt * 16 + half * 8;
            float2 v0 = make_float2(0.f, 0.f), v1 = v0;
            if (r < M) {
                const float* p = A + (size_t)r * D_N + kk + lc;
                v0 = *reinterpret_cast<const float2*>(p);
                v1 = *reinterpret_cast<const float2*>(p + 8);
            }
            xa[mt][half] = v0;
            xb[mt][half] = v1;
        }
}

__global__ void __launch_bounds__(256)
gemm_mma_kernel(const float* __restrict__ A0, const float* __restrict__ A1,
                const float* __restrict__ A2,
                const uint4* __restrict__ Bfrag, const float* __restrict__ bias,
                float* __restrict__ out, int M, int nseg,
                const float* __restrict__ Wh, const float* __restrict__ bh,
                float* __restrict__ head_out) {
    __shared__ float bsh[128];
    __shared__ float wsh[NHEADS][128];
    __shared__ float bhs[NHEADS];
    __shared__ uint4 bsm[2][512];   // double-buffered 8 KB B k-tile images

    const int tid  = threadIdx.x;
    const int lane = tid & 31;
    const int wid  = tid >> 5;
    const int row0 = blockIdx.x * 256;

    if (tid < 128) bsh[tid] = bias[tid];
    if (head_out) {
        for (int i = tid; i < NHEADS * 128; i += 256) wsh[i >> 7][i & 127] = Wh[i];
        if (tid < NHEADS) bhs[tid] = bh[tid];
    }

    const int K16 = nseg * 8;

    // stage k-tile 0 into buffer 0; prefetch k-tile 1 into regs
    {
        uint4 t0 = Bfrag[tid];
        uint4 t1 = Bfrag[tid + 256];
        bsm[0][tid] = t0;
        bsm[0][tid + 256] = t1;
    }
    uint4 pb0, pb1;
    if (K16 > 1) {
        pb0 = Bfrag[512 + tid];
        pb1 = Bfrag[512 + tid + 256];
    }
    __syncthreads();

    const int lr  = lane >> 2;
    const int lc  = (lane & 3) * 2;
    const int row_lo = row0 + wid * 32 + lr;

    float c[2][16][4] = {};

    float2 ra[2][2], rb[2][2], na[2][2], nb[2][2];
    load_rawA(A0, A1, A2, 0, row_lo, lc, M, ra, rb);

    for (int kt = 0; kt < K16; ++kt) {
        const int cur = kt & 1;
        const int nxt = cur ^ 1;

        if (kt + 1 < K16) {
            bsm[nxt][tid] = pb0;
            bsm[nxt][tid + 256] = pb1;
        }
        if (kt + 2 < K16) {
            pb0 = Bfrag[(size_t)(kt + 2) * 512 + tid];
            pb1 = Bfrag[(size_t)(kt + 2) * 512 + tid + 256];
        }
        if (kt + 1 < K16)
            load_rawA(A0, A1, A2, kt + 1, row_lo, lc, M, na, nb);

        uint32_t ah[2][4], al[2][4];
        #pragma unroll
        for (int mt = 0; mt < 2; ++mt)
            #pragma unroll
            for (int half = 0; half < 2; ++half) {
                split_pack(ra[mt][half].x, ra[mt][half].y, ah[mt][half], al[mt][half]);
                split_pack(rb[mt][half].x, rb[mt][half].y, ah[mt][2 + half], al[mt][2 + half]);
            }

        #pragma unroll
        for (int nt = 0; nt < 16; ++nt) {
            uint4 b = bsm[cur][nt * 32 + lane];
            #pragma unroll
            for (int mt = 0; mt < 2; ++mt) {
                mma_bf16(c[mt][nt], ah[mt], b.x, b.y);
                mma_bf16(c[mt][nt], al[mt], b.x, b.y);
                mma_bf16(c[mt][nt], ah[mt], b.z, b.w);
            }
        }
        __syncthreads();

        #pragma unroll
        for (int mt = 0; mt < 2; ++mt)
            #pragma unroll
            for (int half = 0; half < 2; ++half) {
                ra[mt][half] = na[mt][half];
                rb[mt][half] = nb[mt][half];
            }
    }

    if (head_out) {
        #pragma unroll
        for (int mt = 0; mt < 2; ++mt) {
            #pragma unroll
            for (int half = 0; half < 2; ++half) {
                int r = row_lo + mt * 16 + half * 8;
                float hp[NHEADS] = {};
                #pragma unroll
                for (int nt = 0; nt < 16; ++nt) {
                    int col = nt * 8 + lc;
                    float v0 = c[mt][nt][half * 2 + 0] + bsh[col];
                    float v1 = c[mt][nt][half * 2 + 1] + bsh[col + 1];
                    v0 = v0 > 0.f ? v0 : 0.01f * v0;
                    v1 = v1 > 0.f ? v1 : 0.01f * v1;
                    #pragma unroll
                    for (int h = 0; h < NHEADS; ++h)
                        hp[h] += v0 * wsh[h][col] + v1 * wsh[h][col + 1];
                }
                #pragma unroll
                for (int h = 0; h < NHEADS; ++h) {
                    hp[h] += __shfl_down_sync(0xffffffffu, hp[h], 2, 4);
                    hp[h] += __shfl_down_sync(0xffffffffu, hp[h], 1, 4);
                }
                if ((lane & 3) == 0 && r < M) {
                    float4 o0 = make_float4(hp[0] + bhs[0], hp[1] + bhs[1],
                                            hp[2] + bhs[2], hp[3] + bhs[3]);
                    float4 o1 = make_float4(hp[4] + bhs[4], hp[5] + bhs[5],
                                            hp[6] + bhs[6], hp[7] + bhs[7]);
                    *reinterpret_cast<float4*>(head_out + (size_t)r * NHEADS)     = o0;
                    *reinterpret_cast<float4*>(head_out + (size_t)r * NHEADS + 4) = o1;
                }
            }
        }
    } else {
        #pragma unroll
        for (int mt = 0; mt < 2; ++mt) {
            #pragma unroll
            for (int nt = 0; nt < 16; ++nt) {
                int col = nt * 8 + lc;
                float b0 = bsh[col], b1 = bsh[col + 1];
                int r0 = row_lo + mt * 16;
                int r1 = r0 + 8;
                if (r0 < M) {
                    float2 o;
                    o.x = c[mt][nt][0] + b0; o.x = o.x > 0.f ? o.x : 0.01f * o.x;
                    o.y = c[mt][nt][1] + b1; o.y = o.y > 0.f ? o.y : 0.01f * o.y;
                    *reinterpret_cast<float2*>(out + (size_t)r0 * D_N + col) = o;
                }
                if (r1 < M) {
                    float2 o;
                    o.x = c[mt][nt][2] + b0; o.x = o.x > 0.f ? o.x : 0.01f * o.x;
                    o.y = c[mt][nt][3] + b1; o.y = o.y > 0.f ? o.y : 0.01f * o.y;
                    *reinterpret_cast<float2*>(out + (size_t)r1 * D_N + col) = o;
                }
            }
        }
    }
}

// ---------------- host launch ----------------
extern "C" void kernel_launch(void* const* d_in, const int* in_sizes, int n_in,
                              void* d_out, int out_size) {
    (void)in_sizes; (void)n_in; (void)out_size;
    const float* x_b  = (const float*)d_in[0];
    const float* x_s  = (const float*)d_in[1];
    const float* Wl   = (const float*)d_in[2];
    const float* bl   = (const float*)d_in[3];
    const float* Wr   = (const float*)d_in[4];
    const float* Wh   = (const float*)d_in[5];
    const float* bh   = (const float*)d_in[6];
    const int*   ei_bb = (const int*)d_in[7];   // JAX x64 off -> int32 indices
    const int*   ei_sb = (const int*)d_in[8];
    const int*   ei_bs = (const int*)d_in[9];

    static cudaStream_t sB = nullptr;
    static cudaEvent_t evFork, evPrep, evFill, evS;
    if (!sB) {
        cudaStreamCreateWithFlags(&sB, cudaStreamNonBlocking);
        cudaEventCreateWithFlags(&evFork, cudaEventDisableTiming);
        cudaEventCreateWithFlags(&evPrep, cudaEventDisableTiming);
        cudaEventCreateWithFlags(&evFill, cudaEventDisableTiming);
        cudaEventCreateWithFlags(&evS,    cudaEventDisableTiming);
    }

    void *p_xb0, *p_xs0, *p_abb, *p_asb, *p_asb2, *p_abs, *p_Bb, *p_Bs, *p_FB, *p_FS;
    cudaGetSymbolAddress(&p_xb0, g_xb0);
    cudaGetSymbolAddress(&p_xs0, g_xs0);
    cudaGetSymbolAddress(&p_abb, g_acc_bb); cudaGetSymbolAddress(&p_asb, g_acc_sb);
    cudaGetSymbolAddress(&p_asb2, g_acc_sb2);
    cudaGetSymbolAddress(&p_abs, g_acc_bs);
    cudaGetSymbolAddress(&p_Bb, g_Bb); cudaGetSymbolAddress(&p_Bs, g_Bs);
    cudaGetSymbolAddress(&p_FB, g_WfragB); cudaGetSymbolAddress(&p_FS, g_WfragS);

    float* xb0 = (float*)p_xb0;
    float* xs0 = (float*)p_xs0;
    float* acc_bb = (float*)p_abb; float* acc_sb = (float*)p_asb;
    float* acc_sb2 = (float*)p_asb2; float* acc_bs = (float*)p_abs;
    float* Bbp = (float*)p_Bb; float* Bsp = (float*)p_Bs;
    const uint4* FragB = (const uint4*)p_FB;
    const uint4* FragS = (const uint4*)p_FS;

    const int T = 256;
    const int NTOT = 2 * NB_N + NS_N;
    const int ETOT = E_BB_N + E_SB_N + E_BS_N;

    // ---- fork ----
    cudaEventRecord(evFork, 0);
    cudaStreamWaitEvent(sB, evFork, 0);

    // stream 0: CSR build (zero -> count -> single-kernel scan -> fill)
    zero_all_kernel<<<(NTOT + T - 1) / T, T>>>();
    count_all_kernel<<<(ETOT + T - 1) / T, T>>>(ei_bb, ei_sb, ei_bs);
    scan_all_kernel<<<3, 1024>>>();
    fill_all_kernel<<<(ETOT + T - 1) / T, T>>>(ei_bb, ei_sb, ei_bs);
    cudaEventRecord(evFill, 0);

    // sB: weight prep (independent of CSR)
    prep_wb_kernel<<<(2 * 384 * 128 + T - 1) / T, T, 0, sB>>>(Wl, bl, Wr);
    prep_ws_kernel<<<(256 * 128 + T - 1) / T, T, 0, sB>>>(Wl, bl, Wr);
    prep_bfrag_b_kernel<<<(2 * 24 * 16 * 32 + T - 1) / T, T, 0, sB>>>();
    prep_bfrag_s_kernel<<<(16 * 16 * 32 + T - 1) / T, T, 0, sB>>>();
    cudaEventRecord(evPrep, sB);

    // stream 0: layer-1 b segmeans (needs CSR only)
    segmean2_kernel<<<(2 * NB_N + 7) / 8, 256>>>(x_b, x_s, acc_bb, acc_sb);

    // sB: s-chain + layer-2 sb segmean
    cudaStreamWaitEvent(sB, evFill, 0);
    segmean_bs_kernel<<<(NS_N + 7) / 8, 256, 0, sB>>>(x_b, acc_bs);
    gemm_mma_kernel<<<(NS_N + 255) / 256, 256, 0, sB>>>(
        acc_bs, x_s, nullptr, FragS, Bsp, xs0, NS_N, 2, nullptr, nullptr, nullptr);
    segmean_sb_kernel<<<(NB_N + 7) / 8, 256, 0, sB>>>(xs0, acc_sb2);
    cudaEventRecord(evS, sB);

    // stream 0: layer-1 b GEMM (needs prep; overlaps with sB's layer-2 sb segmean)
    cudaStreamWaitEvent(0, evPrep, 0);
    gemm_mma_kernel<<<(NB_N + 255) / 256, 256>>>(
        acc_bb, acc_sb, x_b, FragB, Bbp, xb0, NB_N, 3, nullptr, nullptr, nullptr);

    // stream 0: layer-2 bb segmean (needs xb0)
    segmean_bb_kernel<<<(NB_N + 7) / 8, 256>>>(xb0, acc_bb);

    // stream 0: layer-2 b GEMM with fused head readout (needs acc_sb2 from sB)
    cudaStreamWaitEvent(0, evS, 0);
    gemm_mma_kernel<<<(NB_N + 255) / 256, 256>>>(
        acc_bb, acc_sb2, xb0, FragB + (size_t)24 * 16 * 32, Bbp + 128,
        nullptr, NB_N, 3, Wh, bh, (float*)d_out);
}

// round 15
// speedup vs baseline: 1.6367x; 1.3690x over previous
#include <cuda_runtime.h>
#include <cuda_bf16.h>
#include <cstdint>
#include <cstddef>

// ---------------- problem constants ----------------
#define NB_N   100000
#define NS_N   50000
#define D_N    128
#define NHEADS 8
#define E_BB_N 800000
#define E_SB_N 400000
#define E_BS_N 400000

// ---------------- device scratch (static; no allocation) ----------------
__device__ float g_xb0[(size_t)NB_N * D_N];
__device__ float g_xs0[(size_t)NS_N * D_N];

__device__ float g_acc_bb[(size_t)NB_N * D_N];
__device__ float g_acc_sb[(size_t)NB_N * D_N];
__device__ float g_acc_sb2[(size_t)NB_N * D_N];   // layer-2 sb mean (overlap buffer)
__device__ float g_acc_bs[(size_t)NS_N * D_N];

// CSR structures per edge type
__device__ int g_cnti_bb[NB_N];
__device__ int g_off_bb[NB_N];
__device__ int g_cur_bb[NB_N];
__device__ int g_perm_bb[E_BB_N];
__device__ int g_cnti_sb[NB_N];
__device__ int g_off_sb[NB_N];
__device__ int g_cur_sb[NB_N];
__device__ int g_perm_sb[E_SB_N];
__device__ int g_cnti_bs[NS_N];
__device__ int g_off_bs[NS_N];
__device__ int g_cur_bs[NS_N];
__device__ int g_perm_bs[E_BS_N];

// dedicated scan-partial buffers (MUST NOT alias cur)
__device__ int g_part_bb[128];
__device__ int g_part_sb[128];
__device__ int g_part_bs[128];

// combined fp32 weights
__device__ float g_Wb[2][384 * 128];
__device__ float g_Bb[2][128];
__device__ float g_Ws[256 * 128];
__device__ float g_Bs[128];

// B in HMMA fragment order: per (ktile, ntile, lane) a uint4 {hi_b0, hi_b1, lo_b0, lo_b1}
__device__ uint4 g_WfragB[2 * 24 * 16 * 32];
__device__ uint4 g_WfragS[16 * 16 * 32];

// ---------------- split-bf16 pack ----------------
__device__ __forceinline__ void split_pack(float v0, float v1, uint32_t& hp, uint32_t& lp) {
    uint32_t b0 = __float_as_uint(v0), b1 = __float_as_uint(v1);
    hp = (b1 & 0xFFFF0000u) | (b0 >> 16);
    float h0 = __uint_as_float(b0 & 0xFFFF0000u);
    float h1 = __uint_as_float(b1 & 0xFFFF0000u);
    asm("cvt.rn.bf16x2.f32 %0, %1, %2;" : "=r"(lp) : "f"(v1 - h1), "f"(v0 - h0));
}

__device__ __forceinline__ void mma_bf16(float* c, const uint32_t* a, uint32_t b0, uint32_t b1) {
    asm volatile("mma.sync.aligned.m16n8k16.row.col.f32.bf16.bf16.f32 "
                 "{%0,%1,%2,%3}, {%4,%5,%6,%7}, {%8,%9}, {%0,%1,%2,%3};"
                 : "+f"(c[0]), "+f"(c[1]), "+f"(c[2]), "+f"(c[3])
                 : "r"(a[0]), "r"(a[1]), "r"(a[2]), "r"(a[3]), "r"(b0), "r"(b1));
}

// ---------------- merged CSR build kernels ----------------
__global__ void zero_all_kernel() {
    int i = blockIdx.x * blockDim.x + threadIdx.x;
    if (i < NB_N)                 g_cnti_bb[i] = 0;
    else if (i < 2 * NB_N)        g_cnti_sb[i - NB_N] = 0;
    else if (i < 2 * NB_N + NS_N) g_cnti_bs[i - 2 * NB_N] = 0;
}
__global__ void count_all_kernel(const int* __restrict__ ei_bb,
                                 const int* __restrict__ ei_sb,
                                 const int* __restrict__ ei_bs) {
    int e = blockIdx.x * blockDim.x + threadIdx.x;
    if (e < E_BB_N) {
        atomicAdd(g_cnti_bb + ei_bb[E_BB_N + e], 1);
    } else if (e < E_BB_N + E_SB_N) {
        int u = e - E_BB_N;
        atomicAdd(g_cnti_sb + ei_sb[E_SB_N + u], 1);
    } else if (e < E_BB_N + E_SB_N + E_BS_N) {
        int u = e - E_BB_N - E_SB_N;
        atomicAdd(g_cnti_bs + ei_bs[E_BS_N + u], 1);
    }
}

#define SCHUNK 1024
#define NCH_B  98
#define NCH_S  49
__device__ __forceinline__ void csr_select(int blk, const int*& cnt, int*& off, int*& cur,
                                           int*& part, int& n, int& b) {
    if (blk < NCH_B)          { cnt = g_cnti_bb; off = g_off_bb; cur = g_cur_bb; part = g_part_bb; n = NB_N; b = blk; }
    else if (blk < 2 * NCH_B) { cnt = g_cnti_sb; off = g_off_sb; cur = g_cur_sb; part = g_part_sb; n = NB_N; b = blk - NCH_B; }
    else                      { cnt = g_cnti_bs; off = g_off_bs; cur = g_cur_bs; part = g_part_bs; n = NS_N; b = blk - 2 * NCH_B; }
}

__global__ void scanA_all_kernel() {
    __shared__ int sh[SCHUNK];
    const int* cnt; int *off, *cur, *part; int n, b;
    csr_select(blockIdx.x, cnt, off, cur, part, n, b);
    int t = threadIdx.x;
    int i = b * SCHUNK + t;
    sh[t] = (i < n) ? cnt[i] : 0;
    __syncthreads();
    #pragma unroll
    for (int s = 512; s > 0; s >>= 1) {
        if (t < s) sh[t] += sh[t + s];
        __syncthreads();
    }
    if (t == 0) part[b] = sh[0];
}
__global__ void scanB_all_kernel() {
    __shared__ int sh[128];
    int* part; int nb;
    if (blockIdx.x == 0)      { part = g_part_bb; nb = NCH_B; }
    else if (blockIdx.x == 1) { part = g_part_sb; nb = NCH_B; }
    else                      { part = g_part_bs; nb = NCH_S; }
    int t = threadIdx.x;
    int v = (t < nb) ? part[t] : 0;
    sh[t] = v;
    __syncthreads();
    #pragma unroll
    for (int s = 1; s < 128; s <<= 1) {
        int a = (t >= s) ? sh[t - s] : 0;
        __syncthreads();
        sh[t] += a;
        __syncthreads();
    }
    if (t < nb) part[t] = sh[t] - v;
}
__global__ void scanC_all_kernel() {
    __shared__ int sh[SCHUNK];
    const int* cnt; int *off, *cur, *part; int n, b;
    csr_select(blockIdx.x, cnt, off, cur, part, n, b);
    int t = threadIdx.x;
    int i = b * SCHUNK + t;
    int v = (i < n) ? cnt[i] : 0;
    sh[t] = v;
    __syncthreads();
    #pragma unroll
    for (int s = 1; s < SCHUNK; s <<= 1) {
        int a = (t >= s) ? sh[t - s] : 0;
        __syncthreads();
        sh[t] += a;
        __syncthreads();
    }
    if (i < n) {
        int ex = sh[t] - v + part[b];
        off[i] = ex;
        cur[i] = ex;
    }
}
__global__ void fill_all_kernel(const int* __restrict__ ei_bb,
                                const int* __restrict__ ei_sb,
                                const int* __restrict__ ei_bs) {
    int e = blockIdx.x * blockDim.x + threadIdx.x;
    if (e < E_BB_N) {
        int p = atomicAdd(g_cur_bb + ei_bb[E_BB_N + e], 1);
        g_perm_bb[p] = ei_bb[e];
    } else if (e < E_BB_N + E_SB_N) {
        int u = e - E_BB_N;
        int p = atomicAdd(g_cur_sb + ei_sb[E_SB_N + u], 1);
        g_perm_sb[p] = ei_sb[u];
    } else if (e < E_BB_N + E_SB_N + E_BS_N) {
        int u = e - E_BB_N - E_SB_N;
        int p = atomicAdd(g_cur_bs + ei_bs[E_BS_N + u], 1);
        g_perm_bs[p] = ei_bs[u];
    }
}

// ---------------- segmented mean core (warp per node, 8-deep MLP) ----------------
__device__ __forceinline__ void segmean_row(const float* __restrict__ x,
                                            const int* __restrict__ perm,
                                            int o, int c, int lane,
                                            float* __restrict__ outrow) {
    float4 acc = make_float4(0.f, 0.f, 0.f, 0.f);
    int i = 0;
    for (; i + 8 <= c; i += 8) {
        float4 v[8];
        #pragma unroll
        for (int j = 0; j < 8; ++j) {
            int s = perm[o + i + j];
            v[j] = reinterpret_cast<const float4*>(x + (size_t)s * D_N)[lane];
        }
        #pragma unroll
        for (int j = 0; j < 8; ++j) {
            acc.x += v[j].x; acc.y += v[j].y; acc.z += v[j].z; acc.w += v[j].w;
        }
    }
    for (; i + 4 <= c; i += 4) {
        float4 v[4];
        #pragma unroll
        for (int j = 0; j < 4; ++j) {
            int s = perm[o + i + j];
            v[j] = reinterpret_cast<const float4*>(x + (size_t)s * D_N)[lane];
        }
        #pragma unroll
        for (int j = 0; j < 4; ++j) {
            acc.x += v[j].x; acc.y += v[j].y; acc.z += v[j].z; acc.w += v[j].w;
        }
    }
    for (; i < c; ++i) {
        int s = perm[o + i];
        float4 v = reinterpret_cast<const float4*>(x + (size_t)s * D_N)[lane];
        acc.x += v.x; acc.y += v.y; acc.z += v.z; acc.w += v.w;
    }
    float inv = (c > 0) ? 1.0f / (float)c : 0.0f;
    acc.x *= inv; acc.y *= inv; acc.z *= inv; acc.w *= inv;
    reinterpret_cast<float4*>(outrow)[lane] = acc;
}

// merged bb + sb segmean (layer 1)
__global__ void __launch_bounds__(256)
segmean2_kernel(const float* __restrict__ xb, const float* __restrict__ xs,
                float* __restrict__ acc_bb, float* __restrict__ acc_sb) {
    int w    = (blockIdx.x * blockDim.x + threadIdx.x) >> 5;
    int lane = threadIdx.x & 31;
    if (w < NB_N) {
        segmean_row(xb, g_perm_bb, g_off_bb[w], g_cnti_bb[w], lane, acc_bb + (size_t)w * D_N);
    } else if (w < 2 * NB_N) {
        int u = w - NB_N;
        segmean_row(xs, g_perm_sb, g_off_sb[u], g_cnti_sb[u], lane, acc_sb + (size_t)u * D_N);
    }
}

__global__ void __launch_bounds__(256)
segmean_bs_kernel(const float* __restrict__ x, float* __restrict__ out) {
    int w    = (blockIdx.x * blockDim.x + threadIdx.x) >> 5;
    int lane = threadIdx.x & 31;
    if (w >= NS_N) return;
    segmean_row(x, g_perm_bs, g_off_bs[w], g_cnti_bs[w], lane, out + (size_t)w * D_N);
}

__global__ void __launch_bounds__(256)
segmean_sb_kernel(const float* __restrict__ x, float* __restrict__ out) {
    int w    = (blockIdx.x * blockDim.x + threadIdx.x) >> 5;
    int lane = threadIdx.x & 31;
    if (w >= NB_N) return;
    segmean_row(x, g_perm_sb, g_off_sb[w], g_cnti_sb[w], lane, out + (size_t)w * D_N);
}

__global__ void __launch_bounds__(256)
segmean_bb_kernel(const float* __restrict__ x, float* __restrict__ out) {
    int w    = (blockIdx.x * blockDim.x + threadIdx.x) >> 5;
    int lane = threadIdx.x & 31;
    if (w >= NB_N) return;
    segmean_row(x, g_perm_bb, g_off_bb[w], g_cnti_bb[w], lane, out + (size_t)w * D_N);
}

// ---------------- weight prep ----------------
__global__ void prep_wb_kernel(const float* __restrict__ Wl, const float* __restrict__ bl,
                               const float* __restrict__ Wr) {
    int idx = blockIdx.x * blockDim.x + threadIdx.x;
    const int total = 2 * 384 * 128;
    if (idx < total) {
        int l = idx / (384 * 128);
        int r = idx % (384 * 128);
        int k = r / 128, n = r % 128;
        float v;
        if (k < 128)      v = Wl[((size_t)(l * 3 + 0) * 128 + k) * 128 + n];
        else if (k < 256) v = Wl[((size_t)(l * 3 + 1) * 128 + (k - 128)) * 128 + n];
        else              v = Wr[((size_t)(l * 3 + 0) * 128 + (k - 256)) * 128 + n]
                            + Wr[((size_t)(l * 3 + 1) * 128 + (k - 256)) * 128 + n];
        g_Wb[l][r] = v;
    }
    if (idx < 2 * 128) {
        int l = idx / 128, n = idx % 128;
        g_Bb[l][n] = bl[(l * 3 + 0) * 128 + n] + bl[(l * 3 + 1) * 128 + n];
    }
}
__global__ void prep_ws_kernel(const float* __restrict__ Wl, const float* __restrict__ bl,
                               const float* __restrict__ Wr) {
    int idx = blockIdx.x * blockDim.x + threadIdx.x;
    const int total = 256 * 128;
    if (idx < total) {
        int k = idx / 128, n = idx % 128;
        float v;
        if (k < 128) v = Wl[((size_t)2 * 128 + k) * 128 + n];
        else         v = Wr[((size_t)2 * 128 + (k - 128)) * 128 + n];
        g_Ws[idx] = v;
    }
    if (idx < 128) g_Bs[idx] = bl[2 * 128 + idx];
}
__global__ void prep_bfrag_b_kernel() {
    int idx = blockIdx.x * blockDim.x + threadIdx.x;
    if (idx >= 2 * 24 * 16 * 32) return;
    int lane = idx & 31;
    int nt   = (idx >> 5) & 15;
    int t    = idx >> 9;
    int kt   = t % 24;
    int l    = t / 24;
    int n  = nt * 8 + (lane >> 2);
    int k0 = kt * 16 + (lane & 3) * 2;
    const float* W = g_Wb[l];
    float v0 = W[(k0 + 0) * 128 + n], v1 = W[(k0 + 1) * 128 + n];
    float v8 = W[(k0 + 8) * 128 + n], v9 = W[(k0 + 9) * 128 + n];
    uint32_t h0, l0, h1, l1;
    split_pack(v0, v1, h0, l0);
    split_pack(v8, v9, h1, l1);
    g_WfragB[idx] = make_uint4(h0, h1, l0, l1);
}
__global__ void prep_bfrag_s_kernel() {
    int idx = blockIdx.x * blockDim.x + threadIdx.x;
    if (idx >= 16 * 16 * 32) return;
    int lane = idx & 31;
    int nt   = (idx >> 5) & 15;
    int kt   = idx >> 9;
    int n  = nt * 8 + (lane >> 2);
    int k0 = kt * 16 + (lane & 3) * 2;
    float v0 = g_Ws[(k0 + 0) * 128 + n], v1 = g_Ws[(k0 + 1) * 128 + n];
    float v8 = g_Ws[(k0 + 8) * 128 + n], v9 = g_Ws[(k0 + 9) * 128 + n];
    uint32_t h0, l0, h1, l1;
    split_pack(v0, v1, h0, l0);
    split_pack(v8, v9, h1, l1);
    g_WfragS[idx] = make_uint4(h0, h1, l0, l1);
}

// ---------------- HMMA fused GEMM + bias + leaky (+ optional head), smem-staged B ------------
// r11 champion config: 256 threads, 8 warps stacked in M, warp tile 32x128.
__device__ __forceinline__ void load_rawA(const float* __restrict__ A0,
                                          const float* __restrict__ A1,
                                          const float* __restrict__ A2,
                                          int kt, int row_lo, int lc, int M,
                                          float2 (&xa)[2][2], float2 (&xb)[2][2]) {
    const int seg = kt >> 3;
    const int kk  = (kt & 7) * 16;
    const float* A = (seg == 0) ? A0 : ((seg == 1) ? A1 : A2);
    #pragma unroll
    for (int mt = 0; mt < 2; ++mt)
        #pragma unroll
        for (int half = 0; half < 2; ++half) {
            int r = row_lo + mt * 16 + half * 8;
            float2 v0 = make_float2(0.f, 0.f), v1 = v0;
            if (r < M) {
                const float* p = A + (size_t)r * D_N + kk + lc;
                v0 = *reinterpret_cast<const float2*>(p);
                v1 = *reinterpret_cast<const float2*>(p + 8);
            }
            xa[mt][half] = v0;
            xb[mt][half] = v1;
        }
}

__global__ void __launch_bounds__(256)
gemm_mma_kernel(const float* __restrict__ A0, const float* __restrict__ A1,
                const float* __restrict__ A2,
                const uint4* __restrict__ Bfrag, const float* __restrict__ bias,
                float* __restrict__ out, int M, int nseg,
                const float* __restrict__ Wh, const float* __restrict__ bh,
                float* __restrict__ head_out) {
    __shared__ float bsh[128];
    __shared__ float wsh[NHEADS][128];
    __shared__ float bhs[NHEADS];
    __shared__ uint4 bsm[2][512];   // double-buffered 8 KB B k-tile images

    const int tid  = threadIdx.x;
    const int lane = tid & 31;
    const int wid  = tid >> 5;
    const int row0 = blockIdx.x * 256;

    if (tid < 128) bsh[tid] = bias[tid];
    if (head_out) {
        for (int i = tid; i < NHEADS * 128; i += 256) wsh[i >> 7][i & 127] = Wh[i];
        if (tid < NHEADS) bhs[tid] = bh[tid];
    }

    const int K16 = nseg * 8;

    // stage k-tile 0 into buffer 0; prefetch k-tile 1 into regs
    {
        uint4 t0 = Bfrag[tid];
        uint4 t1 = Bfrag[tid + 256];
        bsm[0][tid] = t0;
        bsm[0][tid + 256] = t1;
    }
    uint4 pb0, pb1;
    if (K16 > 1) {
        pb0 = Bfrag[512 + tid];
        pb1 = Bfrag[512 + tid + 256];
    }
    __syncthreads();

    const int lr  = lane >> 2;
    const int lc  = (lane & 3) * 2;
    const int row_lo = row0 + wid * 32 + lr;

    float c[2][16][4] = {};

    float2 ra[2][2], rb[2][2], na[2][2], nb[2][2];
    load_rawA(A0, A1, A2, 0, row_lo, lc, M, ra, rb);

    for (int kt = 0; kt < K16; ++kt) {
        const int cur = kt & 1;
        const int nxt = cur ^ 1;

        if (kt + 1 < K16) {
            bsm[nxt][tid] = pb0;
            bsm[nxt][tid + 256] = pb1;
        }
        if (kt + 2 < K16) {
            pb0 = Bfrag[(size_t)(kt + 2) * 512 + tid];
            pb1 = Bfrag[(size_t)(kt + 2) * 512 + tid + 256];
        }
        if (kt + 1 < K16)
            load_rawA(A0, A1, A2, kt + 1, row_lo, lc, M, na, nb);

        uint32_t ah[2][4], al[2][4];
        #pragma unroll
        for (int mt = 0; mt < 2; ++mt)
            #pragma unroll
            for (int half = 0; half < 2; ++half) {
                split_pack(ra[mt][half].x, ra[mt][half].y, ah[mt][half], al[mt][half]);
                split_pack(rb[mt][half].x, rb[mt][half].y, ah[mt][2 + half], al[mt][2 + half]);
            }

        #pragma unroll
        for (int nt = 0; nt < 16; ++nt) {
            uint4 b = bsm[cur][nt * 32 + lane];
            #pragma unroll
            for (int mt = 0; mt < 2; ++mt) {
                mma_bf16(c[mt][nt], ah[mt], b.x, b.y);
                mma_bf16(c[mt][nt], al[mt], b.x, b.y);
                mma_bf16(c[mt][nt], ah[mt], b.z, b.w);
            }
        }
        __syncthreads();

        #pragma unroll
        for (int mt = 0; mt < 2; ++mt)
            #pragma unroll
            for (int half = 0; half < 2; ++half) {
                ra[mt][half] = na[mt][half];
                rb[mt][half] = nb[mt][half];
            }
    }

    if (head_out) {
        #pragma unroll
        for (int mt = 0; mt < 2; ++mt) {
            #pragma unroll
            for (int half = 0; half < 2; ++half) {
                int r = row_lo + mt * 16 + half * 8;
                float hp[NHEADS] = {};
                #pragma unroll
                for (int nt = 0; nt < 16; ++nt) {
                    int col = nt * 8 + lc;
                    float v0 = c[mt][nt][half * 2 + 0] + bsh[col];
                    float v1 = c[mt][nt][half * 2 + 1] + bsh[col + 1];
                    v0 = v0 > 0.f ? v0 : 0.01f * v0;
                    v1 = v1 > 0.f ? v1 : 0.01f * v1;
                    #pragma unroll
                    for (int h = 0; h < NHEADS; ++h)
                        hp[h] += v0 * wsh[h][col] + v1 * wsh[h][col + 1];
                }
                #pragma unroll
                for (int h = 0; h < NHEADS; ++h) {
                    hp[h] += __shfl_down_sync(0xffffffffu, hp[h], 2, 4);
                    hp[h] += __shfl_down_sync(0xffffffffu, hp[h], 1, 4);
                }
                if ((lane & 3) == 0 && r < M) {
                    float4 o0 = make_float4(hp[0] + bhs[0], hp[1] + bhs[1],
                                            hp[2] + bhs[2], hp[3] + bhs[3]);
                    float4 o1 = make_float4(hp[4] + bhs[4], hp[5] + bhs[5],
                                            hp[6] + bhs[6], hp[7] + bhs[7]);
                    *reinterpret_cast<float4*>(head_out + (size_t)r * NHEADS)     = o0;
                    *reinterpret_cast<float4*>(head_out + (size_t)r * NHEADS + 4) = o1;
                }
            }
        }
    } else {
        #pragma unroll
        for (int mt = 0; mt < 2; ++mt) {
            #pragma unroll
            for (int nt = 0; nt < 16; ++nt) {
                int col = nt * 8 + lc;
                float b0 = bsh[col], b1 = bsh[col + 1];
                int r0 = row_lo + mt * 16;
                int r1 = r0 + 8;
                if (r0 < M) {
                    float2 o;
                    o.x = c[mt][nt][0] + b0; o.x = o.x > 0.f ? o.x : 0.01f * o.x;
                    o.y = c[mt][nt][1] + b1; o.y = o.y > 0.f ? o.y : 0.01f * o.y;
                    *reinterpret_cast<float2*>(out + (size_t)r0 * D_N + col) = o;
                }
                if (r1 < M) {
                    float2 o;
                    o.x = c[mt][nt][2] + b0; o.x = o.x > 0.f ? o.x : 0.01f * o.x;
                    o.y = c[mt][nt][3] + b1; o.y = o.y > 0.f ? o.y : 0.01f * o.y;
                    *reinterpret_cast<float2*>(out + (size_t)r1 * D_N + col) = o;
                }
            }
        }
    }
}

// ---------------- host launch ----------------
extern "C" void kernel_launch(void* const* d_in, const int* in_sizes, int n_in,
                              void* d_out, int out_size) {
    (void)in_sizes; (void)n_in; (void)out_size;
    const float* x_b  = (const float*)d_in[0];
    const float* x_s  = (const float*)d_in[1];
    const float* Wl   = (const float*)d_in[2];
    const float* bl   = (const float*)d_in[3];
    const float* Wr   = (const float*)d_in[4];
    const float* Wh   = (const float*)d_in[5];
    const float* bh   = (const float*)d_in[6];
    const int*   ei_bb = (const int*)d_in[7];   // JAX x64 off -> int32 indices
    const int*   ei_sb = (const int*)d_in[8];
    const int*   ei_bs = (const int*)d_in[9];

    static cudaStream_t sB = nullptr;
    static cudaEvent_t evFork, evPrep, evFill, evS;
    if (!sB) {
        cudaStreamCreateWithFlags(&sB, cudaStreamNonBlocking);
        cudaEventCreateWithFlags(&evFork, cudaEventDisableTiming);
        cudaEventCreateWithFlags(&evPrep, cudaEventDisableTiming);
        cudaEventCreateWithFlags(&evFill, cudaEventDisableTiming);
        cudaEventCreateWithFlags(&evS,    cudaEventDisableTiming);
    }

    void *p_xb0, *p_xs0, *p_abb, *p_asb, *p_asb2, *p_abs, *p_Bb, *p_Bs, *p_FB, *p_FS;
    cudaGetSymbolAddress(&p_xb0, g_xb0);
    cudaGetSymbolAddress(&p_xs0, g_xs0);
    cudaGetSymbolAddress(&p_abb, g_acc_bb); cudaGetSymbolAddress(&p_asb, g_acc_sb);
    cudaGetSymbolAddress(&p_asb2, g_acc_sb2);
    cudaGetSymbolAddress(&p_abs, g_acc_bs);
    cudaGetSymbolAddress(&p_Bb, g_Bb); cudaGetSymbolAddress(&p_Bs, g_Bs);
    cudaGetSymbolAddress(&p_FB, g_WfragB); cudaGetSymbolAddress(&p_FS, g_WfragS);

    float* xb0 = (float*)p_xb0;
    float* xs0 = (float*)p_xs0;
    float* acc_bb = (float*)p_abb; float* acc_sb = (float*)p_asb;
    float* acc_sb2 = (float*)p_asb2; float* acc_bs = (float*)p_abs;
    float* Bbp = (float*)p_Bb; float* Bsp = (float*)p_Bs;
    const uint4* FragB = (const uint4*)p_FB;
    const uint4* FragS = (const uint4*)p_FS;

    const int T = 256;
    const int NTOT = 2 * NB_N + NS_N;
    const int ETOT = E_BB_N + E_SB_N + E_BS_N;

    // ---- fork ----
    cudaEventRecord(evFork, 0);
    cudaStreamWaitEvent(sB, evFork, 0);

    // stream 0: CSR build (hierarchical parallel scan — r11 structure)
    zero_all_kernel<<<(NTOT + T - 1) / T, T>>>();
    count_all_kernel<<<(ETOT + T - 1) / T, T>>>(ei_bb, ei_sb, ei_bs);
    scanA_all_kernel<<<2 * NCH_B + NCH_S, SCHUNK>>>();
    scanB_all_kernel<<<3, 128>>>();
    scanC_all_kernel<<<2 * NCH_B + NCH_S, SCHUNK>>>();
    fill_all_kernel<<<(ETOT + T - 1) / T, T>>>(ei_bb, ei_sb, ei_bs);
    cudaEventRecord(evFill, 0);

    // sB: weight prep (independent of CSR)
    prep_wb_kernel<<<(2 * 384 * 128 + T - 1) / T, T, 0, sB>>>(Wl, bl, Wr);
    prep_ws_kernel<<<(256 * 128 + T - 1) / T, T, 0, sB>>>(Wl, bl, Wr);
    prep_bfrag_b_kernel<<<(2 * 24 * 16 * 32 + T - 1) / T, T, 0, sB>>>();
    prep_bfrag_s_kernel<<<(16 * 16 * 32 + T - 1) / T, T, 0, sB>>>();
    cudaEventRecord(evPrep, sB);

    // stream 0: layer-1 b segmeans (needs CSR only)
    segmean2_kernel<<<(2 * NB_N + 7) / 8, 256>>>(x_b, x_s, acc_bb, acc_sb);

    // sB: s-chain + layer-2 sb segmean
    cudaStreamWaitEvent(sB, evFill, 0);
    segmean_bs_kernel<<<(NS_N + 7) / 8, 256, 0, sB>>>(x_b, acc_bs);
    gemm_mma_kernel<<<(NS_N + 255) / 256, 256, 0, sB>>>(
        acc_bs, x_s, nullptr, FragS, Bsp, xs0, NS_N, 2, nullptr, nullptr, nullptr);
    segmean_sb_kernel<<<(NB_N + 7) / 8, 256, 0, sB>>>(xs0, acc_sb2);
    cudaEventRecord(evS, sB);

    // stream 0: layer-1 b GEMM (needs prep; overlaps with sB's layer-2 sb segmean)
    cudaStreamWaitEvent(0, evPrep, 0);
    gemm_mma_kernel<<<(NB_N + 255) / 256, 256>>>(
        acc_bb, acc_sb, x_b, FragB, Bbp, xb0, NB_N, 3, nullptr, nullptr, nullptr);

    // stream 0: layer-2 bb segmean (needs xb0)
    segmean_bb_kernel<<<(NB_N + 7) / 8, 256>>>(xb0, acc_bb);

    // stream 0: layer-2 b GEMM with fused head readout (needs acc_sb2 from sB)
    cudaStreamWaitEvent(0, evS, 0);
    gemm_mma_kernel<<<(NB_N + 255) / 256, 256>>>(
        acc_bb, acc_sb2, xb0, FragB + (size_t)24 * 16 * 32, Bbp + 128,
        nullptr, NB_N, 3, Wh, bh, (float*)d_out);
}

// round 16
// speedup vs baseline: 1.6387x; 1.0012x over previous
#include <cuda_runtime.h>
#include <cuda_bf16.h>
#include <cstdint>
#include <cstddef>

// ---------------- problem constants ----------------
#define NB_N   100000
#define NS_N   50000
#define D_N    128
#define NHEADS 8
#define E_BB_N 800000
#define E_SB_N 400000
#define E_BS_N 400000

// ---------------- device scratch (static; no allocation) ----------------
__device__ float g_xb0[(size_t)NB_N * D_N];
__device__ float g_xs0[(size_t)NS_N * D_N];

__device__ float g_acc_bb[(size_t)NB_N * D_N];
__device__ float g_acc_sb[(size_t)NB_N * D_N];
__device__ float g_acc_sb2[(size_t)NB_N * D_N];   // layer-2 sb mean (overlap buffer)
__device__ float g_acc_bs[(size_t)NS_N * D_N];

// CSR structures per edge type
__device__ int g_cnti_bb[NB_N];
__device__ int g_off_bb[NB_N];
__device__ int g_cur_bb[NB_N];
__device__ int g_perm_bb[E_BB_N];
__device__ int g_cnti_sb[NB_N];
__device__ int g_off_sb[NB_N];
__device__ int g_cur_sb[NB_N];
__device__ int g_perm_sb[E_SB_N];
__device__ int g_cnti_bs[NS_N];
__device__ int g_off_bs[NS_N];
__device__ int g_cur_bs[NS_N];
__device__ int g_perm_bs[E_BS_N];

// dedicated scan-partial buffers (MUST NOT alias cur)
__device__ int g_part_bb[128];
__device__ int g_part_sb[128];
__device__ int g_part_bs[128];

// combined fp32 weights
__device__ float g_Wb[2][384 * 128];
__device__ float g_Bb[2][128];
__device__ float g_Ws[256 * 128];
__device__ float g_Bs[128];

// B in HMMA fragment order: per (ktile, ntile, lane) a uint4 {hi_b0, hi_b1, lo_b0, lo_b1}
__device__ uint4 g_WfragB[2 * 24 * 16 * 32];
__device__ uint4 g_WfragS[16 * 16 * 32];

// ---------------- split-bf16 pack: hi = truncate (single PRMT), lo = RN(residual) ------------
__device__ __forceinline__ void split_pack(float v0, float v1, uint32_t& hp, uint32_t& lp) {
    uint32_t b0 = __float_as_uint(v0), b1 = __float_as_uint(v1);
    hp = __byte_perm(b0, b1, 0x7632);                 // {hi16(b1), hi16(b0)} in one PRMT
    float h0 = __uint_as_float(b0 & 0xFFFF0000u);
    float h1 = __uint_as_float(b1 & 0xFFFF0000u);
    asm("cvt.rn.bf16x2.f32 %0, %1, %2;" : "=r"(lp) : "f"(v1 - h1), "f"(v0 - h0));
}

__device__ __forceinline__ void mma_bf16(float* c, const uint32_t* a, uint32_t b0, uint32_t b1) {
    asm volatile("mma.sync.aligned.m16n8k16.row.col.f32.bf16.bf16.f32 "
                 "{%0,%1,%2,%3}, {%4,%5,%6,%7}, {%8,%9}, {%0,%1,%2,%3};"
                 : "+f"(c[0]), "+f"(c[1]), "+f"(c[2]), "+f"(c[3])
                 : "r"(a[0]), "r"(a[1]), "r"(a[2]), "r"(a[3]), "r"(b0), "r"(b1));
}

// ---------------- merged CSR build kernels ----------------
__global__ void zero_all_kernel() {
    int i = blockIdx.x * blockDim.x + threadIdx.x;
    if (i < NB_N)                 g_cnti_bb[i] = 0;
    else if (i < 2 * NB_N)        g_cnti_sb[i - NB_N] = 0;
    else if (i < 2 * NB_N + NS_N) g_cnti_bs[i - 2 * NB_N] = 0;
}
__global__ void count_all_kernel(const int* __restrict__ ei_bb,
                                 const int* __restrict__ ei_sb,
                                 const int* __restrict__ ei_bs) {
    int e = blockIdx.x * blockDim.x + threadIdx.x;
    if (e < E_BB_N) {
        atomicAdd(g_cnti_bb + ei_bb[E_BB_N + e], 1);
    } else if (e < E_BB_N + E_SB_N) {
        int u = e - E_BB_N;
        atomicAdd(g_cnti_sb + ei_sb[E_SB_N + u], 1);
    } else if (e < E_BB_N + E_SB_N + E_BS_N) {
        int u = e - E_BB_N - E_SB_N;
        atomicAdd(g_cnti_bs + ei_bs[E_BS_N + u], 1);
    }
}

#define SCHUNK 1024
#define NCH_B  98
#define NCH_S  49
__device__ __forceinline__ void csr_select(int blk, const int*& cnt, int*& off, int*& cur,
                                           int*& part, int& n, int& b) {
    if (blk < NCH_B)          { cnt = g_cnti_bb; off = g_off_bb; cur = g_cur_bb; part = g_part_bb; n = NB_N; b = blk; }
    else if (blk < 2 * NCH_B) { cnt = g_cnti_sb; off = g_off_sb; cur = g_cur_sb; part = g_part_sb; n = NB_N; b = blk - NCH_B; }
    else                      { cnt = g_cnti_bs; off = g_off_bs; cur = g_cur_bs; part = g_part_bs; n = NS_N; b = blk - 2 * NCH_B; }
}

__global__ void scanA_all_kernel() {
    __shared__ int sh[SCHUNK];
    const int* cnt; int *off, *cur, *part; int n, b;
    csr_select(blockIdx.x, cnt, off, cur, part, n, b);
    int t = threadIdx.x;
    int i = b * SCHUNK + t;
    sh[t] = (i < n) ? cnt[i] : 0;
    __syncthreads();
    #pragma unroll
    for (int s = 512; s > 0; s >>= 1) {
        if (t < s) sh[t] += sh[t + s];
        __syncthreads();
    }
    if (t == 0) part[b] = sh[0];
}
__global__ void scanB_all_kernel() {
    __shared__ int sh[128];
    int* part; int nb;
    if (blockIdx.x == 0)      { part = g_part_bb; nb = NCH_B; }
    else if (blockIdx.x == 1) { part = g_part_sb; nb = NCH_B; }
    else                      { part = g_part_bs; nb = NCH_S; }
    int t = threadIdx.x;
    int v = (t < nb) ? part[t] : 0;
    sh[t] = v;
    __syncthreads();
    #pragma unroll
    for (int s = 1; s < 128; s <<= 1) {
        int a = (t >= s) ? sh[t - s] : 0;
        __syncthreads();
        sh[t] += a;
        __syncthreads();
    }
    if (t < nb) part[t] = sh[t] - v;
}
__global__ void scanC_all_kernel() {
    __shared__ int sh[SCHUNK];
    const int* cnt; int *off, *cur, *part; int n, b;
    csr_select(blockIdx.x, cnt, off, cur, part, n, b);
    int t = threadIdx.x;
    int i = b * SCHUNK + t;
    int v = (i < n) ? cnt[i] : 0;
    sh[t] = v;
    __syncthreads();
    #pragma unroll
    for (int s = 1; s < SCHUNK; s <<= 1) {
        int a = (t >= s) ? sh[t - s] : 0;
        __syncthreads();
        sh[t] += a;
        __syncthreads();
    }
    if (i < n) {
        int ex = sh[t] - v + part[b];
        off[i] = ex;
        cur[i] = ex;
    }
}
__global__ void fill_all_kernel(const int* __restrict__ ei_bb,
                                const int* __restrict__ ei_sb,
                                const int* __restrict__ ei_bs) {
    int e = blockIdx.x * blockDim.x + threadIdx.x;
    if (e < E_BB_N) {
        int p = atomicAdd(g_cur_bb + ei_bb[E_BB_N + e], 1);
        g_perm_bb[p] = ei_bb[e];
    } else if (e < E_BB_N + E_SB_N) {
        int u = e - E_BB_N;
        int p = atomicAdd(g_cur_sb + ei_sb[E_SB_N + u], 1);
        g_perm_sb[p] = ei_sb[u];
    } else if (e < E_BB_N + E_SB_N + E_BS_N) {
        int u = e - E_BB_N - E_SB_N;
        int p = atomicAdd(g_cur_bs + ei_bs[E_BS_N + u], 1);
        g_perm_bs[p] = ei_bs[u];
    }
}

// ---------------- segmented mean core (warp per node, 8-deep MLP) ----------------
__device__ __forceinline__ void segmean_row(const float* __restrict__ x,
                                            const int* __restrict__ perm,
                                            int o, int c, int lane,
                                            float* __restrict__ outrow) {
    float4 acc = make_float4(0.f, 0.f, 0.f, 0.f);
    int i = 0;
    for (; i + 8 <= c; i += 8) {
        float4 v[8];
        #pragma unroll
        for (int j = 0; j < 8; ++j) {
            int s = perm[o + i + j];
            v[j] = reinterpret_cast<const float4*>(x + (size_t)s * D_N)[lane];
        }
        #pragma unroll
        for (int j = 0; j < 8; ++j) {
            acc.x += v[j].x; acc.y += v[j].y; acc.z += v[j].z; acc.w += v[j].w;
        }
    }
    for (; i + 4 <= c; i += 4) {
        float4 v[4];
        #pragma unroll
        for (int j = 0; j < 4; ++j) {
            int s = perm[o + i + j];
            v[j] = reinterpret_cast<const float4*>(x + (size_t)s * D_N)[lane];
        }
        #pragma unroll
        for (int j = 0; j < 4; ++j) {
            acc.x += v[j].x; acc.y += v[j].y; acc.z += v[j].z; acc.w += v[j].w;
        }
    }
    for (; i < c; ++i) {
        int s = perm[o + i];
        float4 v = reinterpret_cast<const float4*>(x + (size_t)s * D_N)[lane];
        acc.x += v.x; acc.y += v.y; acc.z += v.z; acc.w += v.w;
    }
    float inv = (c > 0) ? 1.0f / (float)c : 0.0f;
    acc.x *= inv; acc.y *= inv; acc.z *= inv; acc.w *= inv;
    reinterpret_cast<float4*>(outrow)[lane] = acc;
}

// merged bb + sb segmean (layer 1)
__global__ void __launch_bounds__(256)
segmean2_kernel(const float* __restrict__ xb, const float* __restrict__ xs,
                float* __restrict__ acc_bb, float* __restrict__ acc_sb) {
    int w    = (blockIdx.x * blockDim.x + threadIdx.x) >> 5;
    int lane = threadIdx.x & 31;
    if (w < NB_N) {
        segmean_row(xb, g_perm_bb, g_off_bb[w], g_cnti_bb[w], lane, acc_bb + (size_t)w * D_N);
    } else if (w < 2 * NB_N) {
        int u = w - NB_N;
        segmean_row(xs, g_perm_sb, g_off_sb[u], g_cnti_sb[u], lane, acc_sb + (size_t)u * D_N);
    }
}

__global__ void __launch_bounds__(256)
segmean_bs_kernel(const float* __restrict__ x, float* __restrict__ out) {
    int w    = (blockIdx.x * blockDim.x + threadIdx.x) >> 5;
    int lane = threadIdx.x & 31;
    if (w >= NS_N) return;
    segmean_row(x, g_perm_bs, g_off_bs[w], g_cnti_bs[w], lane, out + (size_t)w * D_N);
}

__global__ void __launch_bounds__(256)
segmean_sb_kernel(const float* __restrict__ x, float* __restrict__ out) {
    int w    = (blockIdx.x * blockDim.x + threadIdx.x) >> 5;
    int lane = threadIdx.x & 31;
    if (w >= NB_N) return;
    segmean_row(x, g_perm_sb, g_off_sb[w], g_cnti_sb[w], lane, out + (size_t)w * D_N);
}

__global__ void __launch_bounds__(256)
segmean_bb_kernel(const float* __restrict__ x, float* __restrict__ out) {
    int w    = (blockIdx.x * blockDim.x + threadIdx.x) >> 5;
    int lane = threadIdx.x & 31;
    if (w >= NB_N) return;
    segmean_row(x, g_perm_bb, g_off_bb[w], g_cnti_bb[w], lane, out + (size_t)w * D_N);
}

// ---------------- weight prep ----------------
__global__ void prep_wb_kernel(const float* __restrict__ Wl, const float* __restrict__ bl,
                               const float* __restrict__ Wr) {
    int idx = blockIdx.x * blockDim.x + threadIdx.x;
    const int total = 2 * 384 * 128;
    if (idx < total) {
        int l = idx / (384 * 128);
        int r = idx % (384 * 128);
        int k = r / 128, n = r % 128;
        float v;
        if (k < 128)      v = Wl[((size_t)(l * 3 + 0) * 128 + k) * 128 + n];
        else if (k < 256) v = Wl[((size_t)(l * 3 + 1) * 128 + (k - 128)) * 128 + n];
        else              v = Wr[((size_t)(l * 3 + 0) * 128 + (k - 256)) * 128 + n]
                            + Wr[((size_t)(l * 3 + 1) * 128 + (k - 256)) * 128 + n];
        g_Wb[l][r] = v;
    }
    if (idx < 2 * 128) {
        int l = idx / 128, n = idx % 128;
        g_Bb[l][n] = bl[(l * 3 + 0) * 128 + n] + bl[(l * 3 + 1) * 128 + n];
    }
}
__global__ void prep_ws_kernel(const float* __restrict__ Wl, const float* __restrict__ bl,
                               const float* __restrict__ Wr) {
    int idx = blockIdx.x * blockDim.x + threadIdx.x;
    const int total = 256 * 128;
    if (idx < total) {
        int k = idx / 128, n = idx % 128;
        float v;
        if (k < 128) v = Wl[((size_t)2 * 128 + k) * 128 + n];
        else         v = Wr[((size_t)2 * 128 + (k - 128)) * 128 + n];
        g_Ws[idx] = v;
    }
    if (idx < 128) g_Bs[idx] = bl[2 * 128 + idx];
}
__global__ void prep_bfrag_b_kernel() {
    int idx = blockIdx.x * blockDim.x + threadIdx.x;
    if (idx >= 2 * 24 * 16 * 32) return;
    int lane = idx & 31;
    int nt   = (idx >> 5) & 15;
    int t    = idx >> 9;
    int kt   = t % 24;
    int l    = t / 24;
    int n  = nt * 8 + (lane >> 2);
    int k0 = kt * 16 + (lane & 3) * 2;
    const float* W = g_Wb[l];
    float v0 = W[(k0 + 0) * 128 + n], v1 = W[(k0 + 1) * 128 + n];
    float v8 = W[(k0 + 8) * 128 + n], v9 = W[(k0 + 9) * 128 + n];
    uint32_t h0, l0, h1, l1;
    split_pack(v0, v1, h0, l0);
    split_pack(v8, v9, h1, l1);
    g_WfragB[idx] = make_uint4(h0, h1, l0, l1);
}
__global__ void prep_bfrag_s_kernel() {
    int idx = blockIdx.x * blockDim.x + threadIdx.x;
    if (idx >= 16 * 16 * 32) return;
    int lane = idx & 31;
    int nt   = (idx >> 5) & 15;
    int kt   = idx >> 9;
    int n  = nt * 8 + (lane >> 2);
    int k0 = kt * 16 + (lane & 3) * 2;
    float v0 = g_Ws[(k0 + 0) * 128 + n], v1 = g_Ws[(k0 + 1) * 128 + n];
    float v8 = g_Ws[(k0 + 8) * 128 + n], v9 = g_Ws[(k0 + 9) * 128 + n];
    uint32_t h0, l0, h1, l1;
    split_pack(v0, v1, h0, l0);
    split_pack(v8, v9, h1, l1);
    g_WfragS[idx] = make_uint4(h0, h1, l0, l1);
}

// ---------------- HMMA fused GEMM + bias + leaky (+ optional head), smem-staged B ------------
// r11 champion config: 256 threads, 8 warps stacked in M, warp tile 32x128.
__device__ __forceinline__ void load_rawA(const float* __restrict__ A0,
                                          const float* __restrict__ A1,
                                          const float* __restrict__ A2,
                                          int kt, int row_lo, int lc, int M,
                                          float2 (&xa)[2][2], float2 (&xb)[2][2]) {
    const int seg = kt >> 3;
    const int kk  = (kt & 7) * 16;
    const float* A = (seg == 0) ? A0 : ((seg == 1) ? A1 : A2);
    #pragma unroll
    for (int mt = 0; mt < 2; ++mt)
        #pragma unroll
        for (int half = 0; half < 2; ++half) {
            int r = row_lo + mt * 16 + half * 8;
            float2 v0 = make_float2(0.f, 0.f), v1 = v0;
            if (r < M) {
                const float* p = A + (size_t)r * D_N + kk + lc;
                v0 = *reinterpret_cast<const float2*>(p);
                v1 = *reinterpret_cast<const float2*>(p + 8);
            }
            xa[mt][half] = v0;
            xb[mt][half] = v1;
        }
}

__global__ void __launch_bounds__(256)
gemm_mma_kernel(const float* __restrict__ A0, const float* __restrict__ A1,
                const float* __restrict__ A2,
                const uint4* __restrict__ Bfrag, const float* __restrict__ bias,
                float* __restrict__ out, int M, int nseg,
                const float* __restrict__ Wh, const float* __restrict__ bh,
                float* __restrict__ head_out) {
    __shared__ float bsh[128];
    __shared__ float wsh[NHEADS][128];
    __shared__ float bhs[NHEADS];
    __shared__ uint4 bsm[2][512];   // double-buffered 8 KB B k-tile images

    const int tid  = threadIdx.x;
    const int lane = tid & 31;
    const int wid  = tid >> 5;
    const int row0 = blockIdx.x * 256;

    if (tid < 128) bsh[tid] = bias[tid];
    if (head_out) {
        for (int i = tid; i < NHEADS * 128; i += 256) wsh[i >> 7][i & 127] = Wh[i];
        if (tid < NHEADS) bhs[tid] = bh[tid];
    }

    const int K16 = nseg * 8;

    // stage k-tile 0 into buffer 0; prefetch k-tile 1 into regs
    {
        uint4 t0 = Bfrag[tid];
        uint4 t1 = Bfrag[tid + 256];
        bsm[0][tid] = t0;
        bsm[0][tid + 256] = t1;
    }
    uint4 pb0, pb1;
    if (K16 > 1) {
        pb0 = Bfrag[512 + tid];
        pb1 = Bfrag[512 + tid + 256];
    }
    __syncthreads();

    const int lr  = lane >> 2;
    const int lc  = (lane & 3) * 2;
    const int row_lo = row0 + wid * 32 + lr;

    float c[2][16][4] = {};

    float2 ra[2][2], rb[2][2], na[2][2], nb[2][2];
    load_rawA(A0, A1, A2, 0, row_lo, lc, M, ra, rb);

    for (int kt = 0; kt < K16; ++kt) {
        const int cur = kt & 1;
        const int nxt = cur ^ 1;

        if (kt + 1 < K16) {
            bsm[nxt][tid] = pb0;
            bsm[nxt][tid + 256] = pb1;
        }
        if (kt + 2 < K16) {
            pb0 = Bfrag[(size_t)(kt + 2) * 512 + tid];
            pb1 = Bfrag[(size_t)(kt + 2) * 512 + tid + 256];
        }
        if (kt + 1 < K16)
            load_rawA(A0, A1, A2, kt + 1, row_lo, lc, M, na, nb);

        uint32_t ah[2][4], al[2][4];
        #pragma unroll
        for (int mt = 0; mt < 2; ++mt)
            #pragma unroll
            for (int half = 0; half < 2; ++half) {
                split_pack(ra[mt][half].x, ra[mt][half].y, ah[mt][half], al[mt][half]);
                split_pack(rb[mt][half].x, rb[mt][half].y, ah[mt][2 + half], al[mt][2 + half]);
            }

        #pragma unroll
        for (int nt = 0; nt < 16; ++nt) {
            uint4 b = bsm[cur][nt * 32 + lane];
            #pragma unroll
            for (int mt = 0; mt < 2; ++mt) {
                mma_bf16(c[mt][nt], ah[mt], b.x, b.y);
                mma_bf16(c[mt][nt], al[mt], b.x, b.y);
                mma_bf16(c[mt][nt], ah[mt], b.z, b.w);
            }
        }
        __syncthreads();

        #pragma unroll
        for (int mt = 0; mt < 2; ++mt)
            #pragma unroll
            for (int half = 0; half < 2; ++half) {
                ra[mt][half] = na[mt][half];
                rb[mt][half] = nb[mt][half];
            }
    }

    if (head_out) {
        #pragma unroll
        for (int mt = 0; mt < 2; ++mt) {
            #pragma unroll
            for (int half = 0; half < 2; ++half) {
                int r = row_lo + mt * 16 + half * 8;
                float hp[NHEADS] = {};
                #pragma unroll
                for (int nt = 0; nt < 16; ++nt) {
                    int col = nt * 8 + lc;
                    float v0 = c[mt][nt][half * 2 + 0] + bsh[col];
                    float v1 = c[mt][nt][half * 2 + 1] + bsh[col + 1];
                    v0 = v0 > 0.f ? v0 : 0.01f * v0;
                    v1 = v1 > 0.f ? v1 : 0.01f * v1;
                    #pragma unroll
                    for (int h = 0; h < NHEADS; ++h)
                        hp[h] += v0 * wsh[h][col] + v1 * wsh[h][col + 1];
                }
                #pragma unroll
                for (int h = 0; h < NHEADS; ++h) {
                    hp[h] += __shfl_down_sync(0xffffffffu, hp[h], 2, 4);
                    hp[h] += __shfl_down_sync(0xffffffffu, hp[h], 1, 4);
                }
                if ((lane & 3) == 0 && r < M) {
                    float4 o0 = make_float4(hp[0] + bhs[0], hp[1] + bhs[1],
                                            hp[2] + bhs[2], hp[3] + bhs[3]);
                    float4 o1 = make_float4(hp[4] + bhs[4], hp[5] + bhs[5],
                                            hp[6] + bhs[6], hp[7] + bhs[7]);
                    *reinterpret_cast<float4*>(head_out + (size_t)r * NHEADS)     = o0;
                    *reinterpret_cast<float4*>(head_out + (size_t)r * NHEADS + 4) = o1;
                }
            }
        }
    } else {
        #pragma unroll
        for (int mt = 0; mt < 2; ++mt) {
            #pragma unroll
            for (int nt = 0; nt < 16; ++nt) {
                int col = nt * 8 + lc;
                float b0 = bsh[col], b1 = bsh[col + 1];
                int r0 = row_lo + mt * 16;
                int r1 = r0 + 8;
                if (r0 < M) {
                    float2 o;
                    o.x = c[mt][nt][0] + b0; o.x = o.x > 0.f ? o.x : 0.01f * o.x;
                    o.y = c[mt][nt][1] + b1; o.y = o.y > 0.f ? o.y : 0.01f * o.y;
                    *reinterpret_cast<float2*>(out + (size_t)r0 * D_N + col) = o;
                }
                if (r1 < M) {
                    float2 o;
                    o.x = c[mt][nt][2] + b0; o.x = o.x > 0.f ? o.x : 0.01f * o.x;
                    o.y = c[mt][nt][3] + b1; o.y = o.y > 0.f ? o.y : 0.01f * o.y;
                    *reinterpret_cast<float2*>(out + (size_t)r1 * D_N + col) = o;
                }
            }
        }
    }
}

// ---------------- host launch ----------------
extern "C" void kernel_launch(void* const* d_in, const int* in_sizes, int n_in,
                              void* d_out, int out_size) {
    (void)in_sizes; (void)n_in; (void)out_size;
    const float* x_b  = (const float*)d_in[0];
    const float* x_s  = (const float*)d_in[1];
    const float* Wl   = (const float*)d_in[2];
    const float* bl   = (const float*)d_in[3];
    const float* Wr   = (const float*)d_in[4];
    const float* Wh   = (const float*)d_in[5];
    const float* bh   = (const float*)d_in[6];
    const int*   ei_bb = (const int*)d_in[7];   // JAX x64 off -> int32 indices
    const int*   ei_sb = (const int*)d_in[8];
    const int*   ei_bs = (const int*)d_in[9];

    static cudaStream_t sB = nullptr;
    static cudaEvent_t evFork, evPrep, evFill, evS;
    if (!sB) {
        cudaStreamCreateWithFlags(&sB, cudaStreamNonBlocking);
        cudaEventCreateWithFlags(&evFork, cudaEventDisableTiming);
        cudaEventCreateWithFlags(&evPrep, cudaEventDisableTiming);
        cudaEventCreateWithFlags(&evFill, cudaEventDisableTiming);
        cudaEventCreateWithFlags(&evS,    cudaEventDisableTiming);
    }

    void *p_xb0, *p_xs0, *p_abb, *p_asb, *p_asb2, *p_abs, *p_Bb, *p_Bs, *p_FB, *p_FS;
    cudaGetSymbolAddress(&p_xb0, g_xb0);
    cudaGetSymbolAddress(&p_xs0, g_xs0);
    cudaGetSymbolAddress(&p_abb, g_acc_bb); cudaGetSymbolAddress(&p_asb, g_acc_sb);
    cudaGetSymbolAddress(&p_asb2, g_acc_sb2);
    cudaGetSymbolAddress(&p_abs, g_acc_bs);
    cudaGetSymbolAddress(&p_Bb, g_Bb); cudaGetSymbolAddress(&p_Bs, g_Bs);
    cudaGetSymbolAddress(&p_FB, g_WfragB); cudaGetSymbolAddress(&p_FS, g_WfragS);

    float* xb0 = (float*)p_xb0;
    float* xs0 = (float*)p_xs0;
    float* acc_bb = (float*)p_abb; float* acc_sb = (float*)p_asb;
    float* acc_sb2 = (float*)p_asb2; float* acc_bs = (float*)p_abs;
    float* Bbp = (float*)p_Bb; float* Bsp = (float*)p_Bs;
    const uint4* FragB = (const uint4*)p_FB;
    const uint4* FragS = (const uint4*)p_FS;

    const int T = 256;
    const int NTOT = 2 * NB_N + NS_N;
    const int ETOT = E_BB_N + E_SB_N + E_BS_N;

    // ---- fork ----
    cudaEventRecord(evFork, 0);
    cudaStreamWaitEvent(sB, evFork, 0);

    // stream 0: CSR build (hierarchical parallel scan)
    zero_all_kernel<<<(NTOT + T - 1) / T, T>>>();
    count_all_kernel<<<(ETOT + T - 1) / T, T>>>(ei_bb, ei_sb, ei_bs);
    scanA_all_kernel<<<2 * NCH_B + NCH_S, SCHUNK>>>();
    scanB_all_kernel<<<3, 128>>>();
    scanC_all_kernel<<<2 * NCH_B + NCH_S, SCHUNK>>>();
    fill_all_kernel<<<(ETOT + T - 1) / T, T>>>(ei_bb, ei_sb, ei_bs);
    cudaEventRecord(evFill, 0);

    // sB: weight prep (independent of CSR)
    prep_wb_kernel<<<(2 * 384 * 128 + T - 1) / T, T, 0, sB>>>(Wl, bl, Wr);
    prep_ws_kernel<<<(256 * 128 + T - 1) / T, T, 0, sB>>>(Wl, bl, Wr);
    prep_bfrag_b_kernel<<<(2 * 24 * 16 * 32 + T - 1) / T, T, 0, sB>>>();
    prep_bfrag_s_kernel<<<(16 * 16 * 32 + T - 1) / T, T, 0, sB>>>();
    cudaEventRecord(evPrep, sB);

    // stream 0: layer-1 b segmeans (needs CSR only)
    segmean2_kernel<<<(2 * NB_N + 7) / 8, 256>>>(x_b, x_s, acc_bb, acc_sb);

    // sB: s-chain + layer-2 sb segmean
    cudaStreamWaitEvent(sB, evFill, 0);
    segmean_bs_kernel<<<(NS_N + 7) / 8, 256, 0, sB>>>(x_b, acc_bs);
    gemm_mma_kernel<<<(NS_N + 255) / 256, 256, 0, sB>>>(
        acc_bs, x_s, nullptr, FragS, Bsp, xs0, NS_N, 2, nullptr, nullptr, nullptr);
    segmean_sb_kernel<<<(NB_N + 7) / 8, 256, 0, sB>>>(xs0, acc_sb2);
    cudaEventRecord(evS, sB);

    // stream 0: layer-1 b GEMM (needs prep; overlaps with sB's layer-2 sb segmean)
    cudaStreamWaitEvent(0, evPrep, 0);
    gemm_mma_kernel<<<(NB_N + 255) / 256, 256>>>(
        acc_bb, acc_sb, x_b, FragB, Bbp, xb0, NB_N, 3, nullptr, nullptr, nullptr);

    // stream 0: layer-2 bb segmean (needs xb0)
    segmean_bb_kernel<<<(NB_N + 7) / 8, 256>>>(xb0, acc_bb);

    // stream 0: layer-2 b GEMM with fused head readout (needs acc_sb2 from sB)
    cudaStreamWaitEvent(0, evS, 0);
    gemm_mma_kernel<<<(NB_N + 255) / 256, 256>>>(
        acc_bb, acc_sb2, xb0, FragB + (size_t)24 * 16 * 32, Bbp + 128,
        nullptr, NB_N, 3, Wh, bh, (float*)d_out);
}